// round 7
// baseline (speedup 1.0000x reference)
#include <cuda_runtime.h>
#include <cuda_bf16.h>
#include <cstdint>

// ---------------------------------------------------------------------------
// out = emb[ids_en] + S @ V,  with vocab collapse:
//   proj = emb @ Qdense [300,512] (precomputed, stored packed bf16 {hi|lo})
// Per batch (ONE CTA): stage P = proj[ids_fr] [64,512] as bf16 hi/lo planes;
//   S = P @ P^T on tensor cores (3-product bf16 split), masked, converted
//   IN-REGISTER from D-fragments to A-fragments (m16n8 D == m16k16 A layout);
//   enc = S @ V where B fragments come from the SAME P planes via
//   ldmatrix.x4.trans. No Gram table, no scattered gathers.
// (tcgen05 unavailable: harness builds through plain compute_103 PTX.)
// ---------------------------------------------------------------------------

namespace {
constexpr int kB = 1024;
constexpr int kV = 300;
constexpr int kD = 512;
constexpr int PROWB = 1040;              // P plane row stride bytes (512 bf16 + 16B pad)
                                         // 260 words % 32 = 4 -> all ldsm conflict-free
constexpr int OFF_PHI = 0;
constexpr int OFF_PLO = 64 * PROWB;          // 66,560
constexpr int DPL     = OFF_PLO - OFF_PHI;
constexpr int OFF_EX  = 2 * 64 * PROWB;      // 133,120 ; 16 warps x 8 regs x 32 lanes
constexpr int OFF_TFR = OFF_EX + 16 * 8 * 32 * 4;   // 149,504
constexpr int OFF_TEN = OFF_TFR + 256;
constexpr int OFF_MFR = OFF_TEN + 256;
constexpr int SMEM_MAIN = OFF_MFR + 256 + 256;       // 150,528 B -> 1 CTA/SM
}

__device__ uint32_t g_projs[kV * kD];    // packed {bf16 hi | bf16 residual-lo}

// ---------------- helpers --------------------------------------------------
__device__ __forceinline__ uint32_t smem_u32(const void* p) {
    uint32_t a;
    asm("{ .reg .u64 t; cvta.to.shared.u64 t, %1; cvt.u32.u64 %0, t; }"
        : "=r"(a) : "l"(p));
    return a;
}
__device__ __forceinline__ uint32_t prmt(uint32_t a, uint32_t b, uint32_t sel) {
    uint32_t d;
    asm("prmt.b32 %0, %1, %2, %3;" : "=r"(d) : "r"(a), "r"(b), "r"(sel));
    return d;
}
__device__ __forceinline__ void ldsm4(uint32_t* r, uint32_t addr) {
    asm volatile("ldmatrix.sync.aligned.m8n8.x4.shared.b16 {%0,%1,%2,%3}, [%4];"
                 : "=r"(r[0]), "=r"(r[1]), "=r"(r[2]), "=r"(r[3]) : "r"(addr));
}
__device__ __forceinline__ void ldsm4t(uint32_t* r, uint32_t addr) {
    asm volatile("ldmatrix.sync.aligned.m8n8.x4.trans.shared.b16 {%0,%1,%2,%3}, [%4];"
                 : "=r"(r[0]), "=r"(r[1]), "=r"(r[2]), "=r"(r[3]) : "r"(addr));
}
__device__ __forceinline__ void mma_bf16(float* c, const uint32_t* a,
                                         const uint32_t* b) {
    asm volatile(
        "mma.sync.aligned.m16n8k16.row.col.f32.bf16.bf16.f32 "
        "{%0,%1,%2,%3}, {%4,%5,%6,%7}, {%8,%9}, {%0,%1,%2,%3};"
        : "+f"(c[0]), "+f"(c[1]), "+f"(c[2]), "+f"(c[3])
        : "r"(a[0]), "r"(a[1]), "r"(a[2]), "r"(a[3]), "r"(b[0]), "r"(b[1]));
}
// (f0, f1) fp32 -> packed bf16x2 hi (f0 low) + packed bf16x2 residual lo
__device__ __forceinline__ void split2(float f0, float f1, uint32_t& hi,
                                       uint32_t& lo) {
    asm("cvt.rn.bf16x2.f32 %0, %1, %2;" : "=r"(hi) : "f"(f1), "f"(f0));
    float h0 = __uint_as_float(hi << 16);
    float h1 = __uint_as_float(hi & 0xFFFF0000u);
    float r0 = f0 - h0, r1 = f1 - h1;
    asm("cvt.rn.bf16x2.f32 %0, %1, %2;" : "=r"(lo) : "f"(r1), "f"(r0));
}
__device__ __forceinline__ uint32_t pack_split(float v) {
    __nv_bfloat16 h = __float2bfloat16(v);
    float hf = __bfloat162float(h);
    __nv_bfloat16 l = __float2bfloat16(v - hf);
    return ((uint32_t)__bfloat16_as_ushort(h) << 16) | __bfloat16_as_ushort(l);
}

// ---------------------------------------------------------------------------
// Kernel 1: proj = emb @ Qdense -> g_projs packed. grid (19,16), 16x32 tiles.
// ---------------------------------------------------------------------------
__global__ void __launch_bounds__(256) proj_kernel(const float* __restrict__ emb,
                                                   const float* __restrict__ Wq) {
    __shared__ float As[16 * 65];
    __shared__ float Bs[64 * 36];
    const int r0 = blockIdx.x * 16, c0 = blockIdx.y * 32;
    const int t = threadIdx.x;
    const int r = t & 15, cg = t >> 4;
    float2 acc = make_float2(0.f, 0.f);

    for (int kc = 0; kc < kD; kc += 64) {
        __syncthreads();
        {
            int ar = t >> 4, ak4 = t & 15;
            float4 v = make_float4(0.f, 0.f, 0.f, 0.f);
            if (r0 + ar < kV) v = *(const float4*)(emb + (r0 + ar) * kD + kc + ak4 * 4);
            float* d = As + ar * 65 + ak4 * 4;
            d[0] = v.x; d[1] = v.y; d[2] = v.z; d[3] = v.w;
        }
        {
            int c4 = t & 7;
#pragma unroll
            for (int j = 0; j < 2; j++) {
                int bk = (t >> 3) + 32 * j;
                float4 v = *(const float4*)(Wq + (kc + bk) * kD + c0 + c4 * 4);
                *(float4*)(Bs + bk * 36 + c4 * 4) = v;
            }
        }
        __syncthreads();
#pragma unroll 8
        for (int kk = 0; kk < 64; kk++) {
            float a = As[r * 65 + kk];
            float2 bv = *(const float2*)(Bs + kk * 36 + cg * 2);
            acc.x = fmaf(a, bv.x, acc.x);
            acc.y = fmaf(a, bv.y, acc.y);
        }
    }
    if (r0 + r < kV) {
        int idx = (r0 + r) * kD + c0 + cg * 2;
        g_projs[idx]     = pack_split(acc.x);
        g_projs[idx + 1] = pack_split(acc.y);
    }
}

// ---------------------------------------------------------------------------
// Kernel 2 (main): grid 1024, 512 threads, 150.5 KB smem, 1 CTA/SM.
// Warp w (0..15): q-tile qt=w&3 (rows 16qt..+16), segment seg=w>>2:
//   S-phase: computes S[q-tile][k' = 16seg..+16] (2 D-tiles) over d=512,
//            masks, splits -> its A-fragment k-tile, exchanged via smem.
//   Main:    enc[q-tile][n = 128seg..+128] with B = ldsm.trans of P planes.
// ---------------------------------------------------------------------------
__global__ void __launch_bounds__(512, 1) main_kernel(
    const int* __restrict__ ids_en, const int* __restrict__ ids_fr,
    const float* __restrict__ emb, float* __restrict__ out) {
    extern __shared__ char smem[];
    const uint32_t sb = smem_u32(smem);
    int* tfr = (int*)(smem + OFF_TFR);
    int* ten = (int*)(smem + OFF_TEN);
    float* mfr = (float*)(smem + OFF_MFR);
    uint32_t* ex = (uint32_t*)(smem + OFF_EX);

    const int b = blockIdx.x;
    const int tid = threadIdx.x;
    if (tid < 64) {
        int t = ids_fr[b * 64 + tid];
        tfr[tid] = t;
        mfr[tid] = t ? 1.f : 0.f;
    } else if (tid < 128) {
        ten[tid - 64] = ids_en[b * 64 + (tid - 64)];
    }
    __syncthreads();

    // ---- Stage P = proj[ids_fr] as bf16 hi/lo planes (coalesced, once) ------
    for (int idx = tid; idx < 64 * 256; idx += 512) {
        int r = idx >> 8, dp = idx & 255;          // dp = d-pair
        uint2 v = __ldg((const uint2*)(g_projs + (size_t)tfr[r] * kD + dp * 2));
        *(uint32_t*)(smem + OFF_PHI + r * PROWB + dp * 4) = prmt(v.x, v.y, 0x7632);
        *(uint32_t*)(smem + OFF_PLO + r * PROWB + dp * 4) = prmt(v.x, v.y, 0x5410);
    }
    __syncthreads();

    const int lane = tid & 31, w = tid >> 5;
    const int qt = w & 3, q0 = qt * 16, seg = w >> 2;

    // ---- S-phase: S[q0..+16][16seg..+16] = P Pt (3-product split) -----------
    const uint32_t aAdr = sb + OFF_PHI
                        + (uint32_t)(q0 + (lane & 15)) * PROWB + (lane >> 4) * 16;
    const uint32_t bAdr = sb + OFF_PHI
                        + (uint32_t)(seg * 16 + (lane & 7) + ((lane >> 4) << 3)) * PROWB
                        + ((lane >> 3) & 1) * 16;
    float sac[2][4] = {{0.f, 0.f, 0.f, 0.f}, {0.f, 0.f, 0.f, 0.f}};
#pragma unroll 4
    for (int ks = 0; ks < 32; ks++) {
        uint32_t aH[4], aL[4], bH[4], bL[4];
        ldsm4(aH, aAdr + ks * 32);
        ldsm4(aL, aAdr + ks * 32 + DPL);
        ldsm4(bH, bAdr + ks * 32);
        ldsm4(bL, bAdr + ks * 32 + DPL);
        mma_bf16(sac[0], aH, bH);     mma_bf16(sac[1], aH, bH + 2);
        mma_bf16(sac[0], aH, bL);     mma_bf16(sac[1], aH, bL + 2);
        mma_bf16(sac[0], aL, bH);     mma_bf16(sac[1], aL, bH + 2);
    }
    // mask + split -> this warp's A-fragment k-tile; publish via exchange
    {
        int colb = seg * 16 + 2 * (lane & 3);
        float m0a = mfr[colb],     m1a = mfr[colb + 1];
        float m0b = mfr[colb + 8], m1b = mfr[colb + 9];
        uint32_t fh[4], fl[4];
        split2(sac[0][0] * m0a, sac[0][1] * m1a, fh[0], fl[0]);
        split2(sac[0][2] * m0a, sac[0][3] * m1a, fh[1], fl[1]);
        split2(sac[1][0] * m0b, sac[1][1] * m1b, fh[2], fl[2]);
        split2(sac[1][2] * m0b, sac[1][3] * m1b, fh[3], fl[3]);
#pragma unroll
        for (int r = 0; r < 4; r++) {
            ex[(w * 8 + r) * 32 + lane]     = fh[r];
            ex[(w * 8 + 4 + r) * 32 + lane] = fl[r];
        }
    }
    __syncthreads();

    // gather full A fragments (k-tiles 0..3) from same-q-tile warps
    uint32_t AH[4][4], AL[4][4];
#pragma unroll
    for (int kt = 0; kt < 4; kt++) {
        int ws = qt + 4 * kt;
#pragma unroll
        for (int r = 0; r < 4; r++) {
            AH[kt][r] = ex[(ws * 8 + r) * 32 + lane];
            AL[kt][r] = ex[(ws * 8 + 4 + r) * 32 + lane];
        }
    }

    // ---- Main GEMM: enc[q-tile][128seg..+128] = S @ V -----------------------
    float acc[16][4];
#pragma unroll
    for (int nt = 0; nt < 16; nt++)
#pragma unroll
        for (int i = 0; i < 4; i++) acc[nt][i] = 0.f;

    const uint32_t btBase = sb + OFF_PHI + (uint32_t)(lane & 15) * PROWB
                          + (uint32_t)(128 * seg + (lane >> 4) * 8) * 2;
#pragma unroll
    for (int ks = 0; ks < 4; ks++) {
#pragma unroll
        for (int ntp = 0; ntp < 8; ntp++) {
            uint32_t adr = btBase + (uint32_t)(ks * 16) * PROWB + ntp * 32;
            uint32_t bH[4], bL[4];
            ldsm4t(bH, adr);
            ldsm4t(bL, adr + DPL);
            mma_bf16(acc[2 * ntp],     AH[ks], bH);
            mma_bf16(acc[2 * ntp],     AH[ks], bL);
            mma_bf16(acc[2 * ntp],     AL[ks], bH);
            mma_bf16(acc[2 * ntp + 1], AH[ks], bH + 2);
            mma_bf16(acc[2 * ntp + 1], AH[ks], bL + 2);
            mma_bf16(acc[2 * ntp + 1], AL[ks], bH + 2);
        }
    }

    // ---- Epilogue: out = enc + emb[ids_en] ----------------------------------
    const int r0 = q0 + (lane >> 2), r1 = r0 + 8;
    const int cb = 128 * seg + 2 * (lane & 3);
    const float* e0 = emb + (size_t)ten[r0] * kD + cb;
    const float* e1 = emb + (size_t)ten[r1] * kD + cb;
    float* o0 = out + ((size_t)b * 64 + r0) * kD + cb;
    float* o1 = out + ((size_t)b * 64 + r1) * kD + cb;
#pragma unroll
    for (int nt = 0; nt < 16; nt++) {
        float2 g0 = __ldg((const float2*)(e0 + nt * 8));
        float2 g1 = __ldg((const float2*)(e1 + nt * 8));
        *(float2*)(o0 + nt * 8) = make_float2(acc[nt][0] + g0.x, acc[nt][1] + g0.y);
        *(float2*)(o1 + nt * 8) = make_float2(acc[nt][2] + g1.x, acc[nt][3] + g1.y);
    }
}

// ---------------------------------------------------------------------------
extern "C" void kernel_launch(void* const* d_in, const int* in_sizes, int n_in,
                              void* d_out, int out_size) {
    (void)in_sizes; (void)n_in; (void)out_size;
    const int* ids_en = (const int*)d_in[0];
    const int* ids_fr = (const int*)d_in[1];
    const float* emb  = (const float*)d_in[2];
    const float* Wq   = (const float*)d_in[3];
    float* out        = (float*)d_out;

    proj_kernel<<<dim3(19, 16), 256>>>(emb, Wq);
    cudaFuncSetAttribute(main_kernel, cudaFuncAttributeMaxDynamicSharedMemorySize,
                         SMEM_MAIN);
    main_kernel<<<kB, 512, SMEM_MAIN>>>(ids_en, ids_fr, emb, out);
}

// round 8
// speedup vs baseline: 1.0456x; 1.0456x over previous
#include <cuda_runtime.h>
#include <cuda_bf16.h>
#include <cstdint>

// ---------------------------------------------------------------------------
// out = emb[ids_en] + S @ V,  vocab collapse:
//   proj = emb @ Qdense [300,512] (precomputed, packed bf16 {hi|lo})
// Per batch (ONE CTA): stage P = proj[ids_fr] bf16 hi/lo planes;
//   S = P P^T on tensor cores (3-product bf16 split) with 32x32 warp tiles x
//   4 d-slices; fp32 partials reduced in smem, masked, split -> S hi/lo
//   planes; enc = S @ V (B = ldsm.trans of the same P planes).
// (tcgen05 unavailable: harness builds through plain compute_103 PTX.)
// ---------------------------------------------------------------------------

namespace {
constexpr int kB = 1024;
constexpr int kV = 300;
constexpr int kD = 512;
constexpr int PROWB = 1040;   // P plane row stride (512 bf16 + 16B) -> ldsm conflict-free
constexpr int SROWB = 144;    // S plane row stride (64 bf16 + 16B)
constexpr int PBSTR = 272;    // partial buffer row stride (68 floats)

constexpr int OFF_PHI = 0;
constexpr int OFF_PLO = OFF_PHI + 64 * PROWB;   // 66,560
constexpr int DPL     = OFF_PLO - OFF_PHI;
constexpr int OFF_SHI = 2 * 64 * PROWB;         // 133,120
constexpr int OFF_SLO = OFF_SHI + 64 * SROWB;   // 142,336
constexpr int DSL     = OFF_SLO - OFF_SHI;
constexpr int OFF_PB  = OFF_SLO + 64 * SROWB;   // 151,552
constexpr int PBDS    = 64 * PBSTR;             // 17,408 per d-slice copy
constexpr int OFF_TFR = OFF_PB + 4 * PBDS;      // 221,184
constexpr int OFF_TEN = OFF_TFR + 256;
constexpr int OFF_MFR = OFF_TEN + 256;
constexpr int SMEM_MAIN = OFF_MFR + 256;        // 221,952 B -> 1 CTA/SM
}

__device__ uint32_t g_projs[kV * kD];    // packed {bf16 hi | bf16 residual-lo}

// ---------------- helpers --------------------------------------------------
__device__ __forceinline__ uint32_t smem_u32(const void* p) {
    uint32_t a;
    asm("{ .reg .u64 t; cvta.to.shared.u64 t, %1; cvt.u32.u64 %0, t; }"
        : "=r"(a) : "l"(p));
    return a;
}
__device__ __forceinline__ uint32_t prmt(uint32_t a, uint32_t b, uint32_t sel) {
    uint32_t d;
    asm("prmt.b32 %0, %1, %2, %3;" : "=r"(d) : "r"(a), "r"(b), "r"(sel));
    return d;
}
__device__ __forceinline__ void ldsm4(uint32_t* r, uint32_t addr) {
    asm volatile("ldmatrix.sync.aligned.m8n8.x4.shared.b16 {%0,%1,%2,%3}, [%4];"
                 : "=r"(r[0]), "=r"(r[1]), "=r"(r[2]), "=r"(r[3]) : "r"(addr));
}
__device__ __forceinline__ void ldsm4t(uint32_t* r, uint32_t addr) {
    asm volatile("ldmatrix.sync.aligned.m8n8.x4.trans.shared.b16 {%0,%1,%2,%3}, [%4];"
                 : "=r"(r[0]), "=r"(r[1]), "=r"(r[2]), "=r"(r[3]) : "r"(addr));
}
__device__ __forceinline__ void mma_bf16(float* c, const uint32_t* a,
                                         const uint32_t* b) {
    asm volatile(
        "mma.sync.aligned.m16n8k16.row.col.f32.bf16.bf16.f32 "
        "{%0,%1,%2,%3}, {%4,%5,%6,%7}, {%8,%9}, {%0,%1,%2,%3};"
        : "+f"(c[0]), "+f"(c[1]), "+f"(c[2]), "+f"(c[3])
        : "r"(a[0]), "r"(a[1]), "r"(a[2]), "r"(a[3]), "r"(b[0]), "r"(b[1]));
}
// (f0, f1) -> packed bf16x2 hi (f0 in low half) + packed bf16x2 residual lo
__device__ __forceinline__ void split2(float f0, float f1, uint32_t& hi,
                                       uint32_t& lo) {
    asm("cvt.rn.bf16x2.f32 %0, %1, %2;" : "=r"(hi) : "f"(f1), "f"(f0));
    float h0 = __uint_as_float(hi << 16);
    float h1 = __uint_as_float(hi & 0xFFFF0000u);
    float r0 = f0 - h0, r1 = f1 - h1;
    asm("cvt.rn.bf16x2.f32 %0, %1, %2;" : "=r"(lo) : "f"(r1), "f"(r0));
}
__device__ __forceinline__ uint32_t pack_split(float v) {
    __nv_bfloat16 h = __float2bfloat16(v);
    float hf = __bfloat162float(h);
    __nv_bfloat16 l = __float2bfloat16(v - hf);
    return ((uint32_t)__bfloat16_as_ushort(h) << 16) | __bfloat16_as_ushort(l);
}

// ---------------------------------------------------------------------------
// Kernel 1: proj = emb @ Qdense -> g_projs packed. (unchanged, known-good)
// ---------------------------------------------------------------------------
__global__ void __launch_bounds__(256) proj_kernel(const float* __restrict__ emb,
                                                   const float* __restrict__ Wq) {
    __shared__ float As[16 * 65];
    __shared__ float Bs[64 * 36];
    const int r0 = blockIdx.x * 16, c0 = blockIdx.y * 32;
    const int t = threadIdx.x;
    const int r = t & 15, cg = t >> 4;
    float2 acc = make_float2(0.f, 0.f);

    for (int kc = 0; kc < kD; kc += 64) {
        __syncthreads();
        {
            int ar = t >> 4, ak4 = t & 15;
            float4 v = make_float4(0.f, 0.f, 0.f, 0.f);
            if (r0 + ar < kV) v = *(const float4*)(emb + (r0 + ar) * kD + kc + ak4 * 4);
            float* d = As + ar * 65 + ak4 * 4;
            d[0] = v.x; d[1] = v.y; d[2] = v.z; d[3] = v.w;
        }
        {
            int c4 = t & 7;
#pragma unroll
            for (int j = 0; j < 2; j++) {
                int bk = (t >> 3) + 32 * j;
                float4 v = *(const float4*)(Wq + (kc + bk) * kD + c0 + c4 * 4);
                *(float4*)(Bs + bk * 36 + c4 * 4) = v;
            }
        }
        __syncthreads();
#pragma unroll 8
        for (int kk = 0; kk < 64; kk++) {
            float a = As[r * 65 + kk];
            float2 bv = *(const float2*)(Bs + kk * 36 + cg * 2);
            acc.x = fmaf(a, bv.x, acc.x);
            acc.y = fmaf(a, bv.y, acc.y);
        }
    }
    if (r0 + r < kV) {
        int idx = (r0 + r) * kD + c0 + cg * 2;
        g_projs[idx]     = pack_split(acc.x);
        g_projs[idx + 1] = pack_split(acc.y);
    }
}

// ---------------------------------------------------------------------------
// Kernel 2 (main): grid 1024, 512 threads, ~217 KB smem, 1 CTA/SM.
// ---------------------------------------------------------------------------
__global__ void __launch_bounds__(512, 1) main_kernel(
    const int* __restrict__ ids_en, const int* __restrict__ ids_fr,
    const float* __restrict__ emb, float* __restrict__ out) {
    extern __shared__ char smem[];
    const uint32_t sb = smem_u32(smem);
    int* tfr = (int*)(smem + OFF_TFR);
    int* ten = (int*)(smem + OFF_TEN);
    float* mfr = (float*)(smem + OFF_MFR);

    const int b = blockIdx.x;
    const int tid = threadIdx.x;
    if (tid < 64) {
        int t = ids_fr[b * 64 + tid];
        tfr[tid] = t;
        mfr[tid] = t ? 1.f : 0.f;
    } else if (tid < 128) {
        ten[tid - 64] = ids_en[b * 64 + (tid - 64)];
    }
    __syncthreads();

    // ---- Stage P = proj[ids_fr] as bf16 hi/lo planes ------------------------
    for (int idx = tid; idx < 64 * 256; idx += 512) {
        int r = idx >> 8, dp = idx & 255;
        uint2 v = __ldg((const uint2*)(g_projs + (size_t)tfr[r] * kD + dp * 2));
        *(uint32_t*)(smem + OFF_PHI + r * PROWB + dp * 4) = prmt(v.x, v.y, 0x7632);
        *(uint32_t*)(smem + OFF_PLO + r * PROWB + dp * 4) = prmt(v.x, v.y, 0x5410);
    }
    __syncthreads();

    const int lane = tid & 31, w = tid >> 5;

    // ---- S-phase: warp = (32x32 tile st = w&3; d-slice ds = w>>2) -----------
    {
        const int sq = (w >> 1) & 1, sk = w & 1, ds = w >> 2;
        const uint32_t dbase = (uint32_t)ds * 256;   // 128 d * 2B
        const uint32_t aA0 = sb + OFF_PHI + dbase
            + (uint32_t)(32 * sq + (lane & 15)) * PROWB + ((lane >> 4) * 16);
        const uint32_t aA1 = aA0 + 16 * PROWB;
        const uint32_t bA0 = sb + OFF_PHI + dbase
            + (uint32_t)(32 * sk + (lane & 7) + ((lane >> 4) << 3)) * PROWB
            + (((lane >> 3) & 1) * 16);
        const uint32_t bA1 = bA0 + 16 * PROWB;

        float sac[2][4][4];
#pragma unroll
        for (int mt = 0; mt < 2; mt++)
#pragma unroll
            for (int nt = 0; nt < 4; nt++)
#pragma unroll
                for (int i = 0; i < 4; i++) sac[mt][nt][i] = 0.f;

#pragma unroll 2
        for (int ks = 0; ks < 8; ks++) {
            uint32_t aH0[4], aH1[4], aL0[4], aL1[4];
            ldsm4(aH0, aA0 + ks * 32);
            ldsm4(aH1, aA1 + ks * 32);
            ldsm4(aL0, aA0 + DPL + ks * 32);
            ldsm4(aL1, aA1 + DPL + ks * 32);
            uint32_t bH0[4], bH1[4], bL0[4], bL1[4];
            ldsm4(bH0, bA0 + ks * 32);
            ldsm4(bH1, bA1 + ks * 32);
            ldsm4(bL0, bA0 + DPL + ks * 32);
            ldsm4(bL1, bA1 + DPL + ks * 32);

            mma_bf16(sac[0][0], aH0, bH0);     mma_bf16(sac[0][1], aH0, bH0 + 2);
            mma_bf16(sac[0][0], aH0, bL0);     mma_bf16(sac[0][1], aH0, bL0 + 2);
            mma_bf16(sac[0][0], aL0, bH0);     mma_bf16(sac[0][1], aL0, bH0 + 2);
            mma_bf16(sac[0][2], aH0, bH1);     mma_bf16(sac[0][3], aH0, bH1 + 2);
            mma_bf16(sac[0][2], aH0, bL1);     mma_bf16(sac[0][3], aH0, bL1 + 2);
            mma_bf16(sac[0][2], aL0, bH1);     mma_bf16(sac[0][3], aL0, bH1 + 2);

            mma_bf16(sac[1][0], aH1, bH0);     mma_bf16(sac[1][1], aH1, bH0 + 2);
            mma_bf16(sac[1][0], aH1, bL0);     mma_bf16(sac[1][1], aH1, bL0 + 2);
            mma_bf16(sac[1][0], aL1, bH0);     mma_bf16(sac[1][1], aL1, bH0 + 2);
            mma_bf16(sac[1][2], aH1, bH1);     mma_bf16(sac[1][3], aH1, bH1 + 2);
            mma_bf16(sac[1][2], aH1, bL1);     mma_bf16(sac[1][3], aH1, bL1 + 2);
            mma_bf16(sac[1][2], aL1, bH1);     mma_bf16(sac[1][3], aL1, bH1 + 2);
        }

        // store fp32 partials to pbuf[ds]
        char* pb = smem + OFF_PB + ds * PBDS;
#pragma unroll
        for (int mt = 0; mt < 2; mt++) {
            int ra = 32 * sq + 16 * mt + (lane >> 2);
#pragma unroll
            for (int nt = 0; nt < 4; nt++) {
                int c = 32 * sk + 8 * nt + 2 * (lane & 3);
                *(float2*)(pb + ra * PBSTR + c * 4) =
                    make_float2(sac[mt][nt][0], sac[mt][nt][1]);
                *(float2*)(pb + (ra + 8) * PBSTR + c * 4) =
                    make_float2(sac[mt][nt][2], sac[mt][nt][3]);
            }
        }
    }
    __syncthreads();

    // ---- Reduce d-slices + mask + split -> S planes; warp w: rows 4w..4w+3 --
    {
        const int c = 2 * lane;
        float m0 = mfr[c], m1 = mfr[c + 1];
#pragma unroll
        for (int rr = 0; rr < 4; rr++) {
            int r = 4 * w + rr;
            const char* pb = smem + OFF_PB + r * PBSTR + c * 4;
            float2 s0 = *(const float2*)pb;
            float2 s1 = *(const float2*)(pb + PBDS);
            float2 s2 = *(const float2*)(pb + 2 * PBDS);
            float2 s3 = *(const float2*)(pb + 3 * PBDS);
            float v0 = ((s0.x + s1.x) + (s2.x + s3.x)) * m0;
            float v1 = ((s0.y + s1.y) + (s2.y + s3.y)) * m1;
            uint32_t hi, lo;
            split2(v0, v1, hi, lo);
            *(uint32_t*)(smem + OFF_SHI + r * SROWB + c * 2) = hi;
            *(uint32_t*)(smem + OFF_SLO + r * SROWB + c * 2) = lo;
        }
    }
    __syncthreads();

    // ---- Main GEMM: warp = (qh = w&1 -> 32 q-rows, seg = w>>1 -> 64 cols) ---
    const int qh = w & 1, seg = w >> 1;
    const uint32_t aS0 = sb + OFF_SHI
        + (uint32_t)(32 * qh + (lane & 15)) * SROWB + ((lane >> 4) * 16);
    const uint32_t aS1 = aS0 + 16 * SROWB;
    const uint32_t bT = sb + OFF_PHI + (uint32_t)(lane & 15) * PROWB
        + (uint32_t)(64 * seg + (lane >> 4) * 8) * 2;

    float acc[2][8][4];
#pragma unroll
    for (int mt = 0; mt < 2; mt++)
#pragma unroll
        for (int nt = 0; nt < 8; nt++)
#pragma unroll
            for (int i = 0; i < 4; i++) acc[mt][nt][i] = 0.f;

#pragma unroll
    for (int ks = 0; ks < 4; ks++) {
        uint32_t AH0[4], AH1[4], AL0[4], AL1[4];
        ldsm4(AH0, aS0 + ks * 32);
        ldsm4(AH1, aS1 + ks * 32);
        ldsm4(AL0, aS0 + DSL + ks * 32);
        ldsm4(AL1, aS1 + DSL + ks * 32);
#pragma unroll
        for (int nt = 0; nt < 4; nt++) {
            uint32_t adr = bT + (uint32_t)(ks * 16) * PROWB + nt * 32;
            uint32_t bH[4], bL[4];
            ldsm4t(bH, adr);
            ldsm4t(bL, adr + DPL);
            mma_bf16(acc[0][2 * nt],     AH0, bH);
            mma_bf16(acc[0][2 * nt],     AH0, bL);
            mma_bf16(acc[0][2 * nt],     AL0, bH);
            mma_bf16(acc[0][2 * nt + 1], AH0, bH + 2);
            mma_bf16(acc[0][2 * nt + 1], AH0, bL + 2);
            mma_bf16(acc[0][2 * nt + 1], AL0, bH + 2);
            mma_bf16(acc[1][2 * nt],     AH1, bH);
            mma_bf16(acc[1][2 * nt],     AH1, bL);
            mma_bf16(acc[1][2 * nt],     AL1, bH);
            mma_bf16(acc[1][2 * nt + 1], AH1, bH + 2);
            mma_bf16(acc[1][2 * nt + 1], AH1, bL + 2);
            mma_bf16(acc[1][2 * nt + 1], AL1, bH + 2);
        }
    }

    // ---- Epilogue: out = enc + emb[ids_en] ----------------------------------
    const int cb = 64 * seg + 2 * (lane & 3);
#pragma unroll
    for (int mt = 0; mt < 2; mt++) {
        int ra = 32 * qh + 16 * mt + (lane >> 2);
        int rb = ra + 8;
        const float* ea = emb + (size_t)ten[ra] * kD + cb;
        const float* eb = emb + (size_t)ten[rb] * kD + cb;
        float* oa = out + ((size_t)b * 64 + ra) * kD + cb;
        float* ob = out + ((size_t)b * 64 + rb) * kD + cb;
#pragma unroll
        for (int nt = 0; nt < 8; nt++) {
            float2 ga = __ldg((const float2*)(ea + nt * 8));
            float2 gb = __ldg((const float2*)(eb + nt * 8));
            *(float2*)(oa + nt * 8) =
                make_float2(acc[mt][nt][0] + ga.x, acc[mt][nt][1] + ga.y);
            *(float2*)(ob + nt * 8) =
                make_float2(acc[mt][nt][2] + gb.x, acc[mt][nt][3] + gb.y);
        }
    }
}

// ---------------------------------------------------------------------------
extern "C" void kernel_launch(void* const* d_in, const int* in_sizes, int n_in,
                              void* d_out, int out_size) {
    (void)in_sizes; (void)n_in; (void)out_size;
    const int* ids_en = (const int*)d_in[0];
    const int* ids_fr = (const int*)d_in[1];
    const float* emb  = (const float*)d_in[2];
    const float* Wq   = (const float*)d_in[3];
    float* out        = (float*)d_out;

    proj_kernel<<<dim3(19, 16), 256>>>(emb, Wq);
    cudaFuncSetAttribute(main_kernel, cudaFuncAttributeMaxDynamicSharedMemorySize,
                         SMEM_MAIN);
    main_kernel<<<kB, 512, SMEM_MAIN>>>(ids_en, ids_fr, emb, out);
}

// round 10
// speedup vs baseline: 1.0785x; 1.0315x over previous
#include <cuda_runtime.h>
#include <cuda_bf16.h>
#include <cstdint>

// ---------------------------------------------------------------------------
// out = emb[ids_en] + S @ V,  vocab collapse:
//   proj = emb @ Qdense [300,512] -> packed bf16 {hi|lo} g_projs (+ fp32)
//   G = proj projT -> packed bf16 {hi|lo} g_grams, stride 304, col 0 zeroed
//     (mask t_k==0 is exactly "column 0 of G" -> pre-zeroed, no select at use)
// Main (per batch, 2 CTAs of 256 cols each, 2 CTAs/SM):
//   stage the 64 needed G ROWS coalesced into smem (aliasing the FULL P
//   hi+lo region, 67.5 KB >= 38.9 KB), column-select -> S hi/lo planes;
//   stage P = proj[ids_fr] (256-col slice) hi/lo planes;
//   enc = S @ V via mma.sync bf16 3-product split; out = enc + emb[ids_en].
// (tcgen05 unavailable: harness builds through plain compute_103 PTX.)
// ---------------------------------------------------------------------------

namespace {
constexpr int kB = 1024;
constexpr int kV = 300;
constexpr int kVP = 304;      // g_grams row stride (words) -> 16B-aligned rows
constexpr int kD = 512;
constexpr int kN = 256;       // cols per main CTA (batch split in 2)
constexpr int PROWB = 528;    // P plane row stride (256 bf16 + 16B)
constexpr int SROWB = 144;    // S plane row stride (64 bf16 + 16B)
constexpr int GSTRB = 1216;   // smem G-row stride bytes (304 words)

constexpr int OFF_PHI = 0;                       // G-row buffer aliases P hi+lo
constexpr int OFF_PLO = OFF_PHI + 64 * PROWB;    // 33,792
constexpr int DPL     = OFF_PLO - OFF_PHI;
constexpr int OFF_SHI = 2 * 64 * PROWB;          // 67,584
constexpr int OFF_SLO = OFF_SHI + 64 * SROWB;    // 76,800
constexpr int DSL     = OFF_SLO - OFF_SHI;
constexpr int OFF_TFR = OFF_SLO + 64 * SROWB;    // 86,016
constexpr int OFF_TEN = OFF_TFR + 256;
constexpr int SMEM_MAIN = OFF_TEN + 256;         // 86,528 B -> 2 CTAs/SM
// G-row buffer (32 rows staged per pass) lives in [OFF_PHI, OFF_SHI):
static_assert(32 * GSTRB <= 2 * 64 * PROWB, "G-row buffer must fit under S planes");
}

__device__ float    g_proj [kV * kD];     // fp32 proj (gram input)
__device__ uint32_t g_projs[kV * kD];     // packed {bf16 hi | bf16 lo}
__device__ uint32_t g_grams[kV * kVP];    // packed gram, col 0 zeroed

// ---------------- helpers --------------------------------------------------
__device__ __forceinline__ uint32_t smem_u32(const void* p) {
    uint32_t a;
    asm("{ .reg .u64 t; cvta.to.shared.u64 t, %1; cvt.u32.u64 %0, t; }"
        : "=r"(a) : "l"(p));
    return a;
}
__device__ __forceinline__ uint32_t prmt(uint32_t a, uint32_t b, uint32_t sel) {
    uint32_t d;
    asm("prmt.b32 %0, %1, %2, %3;" : "=r"(d) : "r"(a), "r"(b), "r"(sel));
    return d;
}
__device__ __forceinline__ void ldsm4(uint32_t* r, uint32_t addr) {
    asm volatile("ldmatrix.sync.aligned.m8n8.x4.shared.b16 {%0,%1,%2,%3}, [%4];"
                 : "=r"(r[0]), "=r"(r[1]), "=r"(r[2]), "=r"(r[3]) : "r"(addr));
}
__device__ __forceinline__ void ldsm4t(uint32_t* r, uint32_t addr) {
    asm volatile("ldmatrix.sync.aligned.m8n8.x4.trans.shared.b16 {%0,%1,%2,%3}, [%4];"
                 : "=r"(r[0]), "=r"(r[1]), "=r"(r[2]), "=r"(r[3]) : "r"(addr));
}
__device__ __forceinline__ void mma_bf16(float* c, const uint32_t* a,
                                         const uint32_t* b) {
    asm volatile(
        "mma.sync.aligned.m16n8k16.row.col.f32.bf16.bf16.f32 "
        "{%0,%1,%2,%3}, {%4,%5,%6,%7}, {%8,%9}, {%0,%1,%2,%3};"
        : "+f"(c[0]), "+f"(c[1]), "+f"(c[2]), "+f"(c[3])
        : "r"(a[0]), "r"(a[1]), "r"(a[2]), "r"(a[3]), "r"(b[0]), "r"(b[1]));
}
__device__ __forceinline__ uint32_t pack_split(float v) {
    __nv_bfloat16 h = __float2bfloat16(v);
    float hf = __bfloat162float(h);
    __nv_bfloat16 l = __float2bfloat16(v - hf);
    return ((uint32_t)__bfloat16_as_ushort(h) << 16) | __bfloat16_as_ushort(l);
}

// ---------------------------------------------------------------------------
// Kernel 1: proj = emb @ Qdense -> g_proj fp32 + g_projs packed.
// ---------------------------------------------------------------------------
__global__ void __launch_bounds__(256) proj_kernel(const float* __restrict__ emb,
                                                   const float* __restrict__ Wq) {
    __shared__ float As[16 * 65];
    __shared__ float Bs[64 * 36];
    const int r0 = blockIdx.x * 16, c0 = blockIdx.y * 32;
    const int t = threadIdx.x;
    const int r = t & 15, cg = t >> 4;
    float2 acc = make_float2(0.f, 0.f);

    for (int kc = 0; kc < kD; kc += 64) {
        __syncthreads();
        {
            int ar = t >> 4, ak4 = t & 15;
            float4 v = make_float4(0.f, 0.f, 0.f, 0.f);
            if (r0 + ar < kV) v = *(const float4*)(emb + (r0 + ar) * kD + kc + ak4 * 4);
            float* d = As + ar * 65 + ak4 * 4;
            d[0] = v.x; d[1] = v.y; d[2] = v.z; d[3] = v.w;
        }
        {
            int c4 = t & 7;
#pragma unroll
            for (int j = 0; j < 2; j++) {
                int bk = (t >> 3) + 32 * j;
                float4 v = *(const float4*)(Wq + (kc + bk) * kD + c0 + c4 * 4);
                *(float4*)(Bs + bk * 36 + c4 * 4) = v;
            }
        }
        __syncthreads();
#pragma unroll 8
        for (int kk = 0; kk < 64; kk++) {
            float a = As[r * 65 + kk];
            float2 bv = *(const float2*)(Bs + kk * 36 + cg * 2);
            acc.x = fmaf(a, bv.x, acc.x);
            acc.y = fmaf(a, bv.y, acc.y);
        }
    }
    if (r0 + r < kV) {
        int idx = (r0 + r) * kD + c0 + cg * 2;
        *(float2*)(g_proj + idx) = acc;
        g_projs[idx]     = pack_split(acc.x);
        g_projs[idx + 1] = pack_split(acc.y);
    }
}

// ---------------------------------------------------------------------------
// Kernel 2: G = proj @ projT -> packed g_grams (stride 304), col 0 zeroed.
// ---------------------------------------------------------------------------
__global__ void __launch_bounds__(256) gram_kernel() {
    __shared__ float As[32 * 130];
    __shared__ float Bs[32 * 130];
    const int i0 = blockIdx.x * 32, j0 = blockIdx.y * 32;
    const int t = threadIdx.x;
    const int tx = t & 15, ty = t >> 4;
    float a00 = 0.f, a01 = 0.f, a10 = 0.f, a11 = 0.f;

    for (int kc = 0; kc < kD; kc += 128) {
        __syncthreads();
        {
            int sr = t >> 3;
#pragma unroll
            for (int j = 0; j < 4; j++) {
                int c4 = (t & 7) + 8 * j;
                float4 va = make_float4(0.f, 0.f, 0.f, 0.f);
                float4 vb = make_float4(0.f, 0.f, 0.f, 0.f);
                if (i0 + sr < kV) va = *(const float4*)(g_proj + (i0 + sr) * kD + kc + c4 * 4);
                if (j0 + sr < kV) vb = *(const float4*)(g_proj + (j0 + sr) * kD + kc + c4 * 4);
                float2* da = (float2*)(As + sr * 130 + c4 * 4);
                float2* db = (float2*)(Bs + sr * 130 + c4 * 4);
                da[0] = make_float2(va.x, va.y); da[1] = make_float2(va.z, va.w);
                db[0] = make_float2(vb.x, vb.y); db[1] = make_float2(vb.z, vb.w);
            }
        }
        __syncthreads();
#pragma unroll 8
        for (int kk = 0; kk < 128; kk += 2) {
            float2 x0 = *(const float2*)(As + ty * 130 + kk);
            float2 x1 = *(const float2*)(As + (ty + 16) * 130 + kk);
            float2 y0 = *(const float2*)(Bs + tx * 130 + kk);
            float2 y1 = *(const float2*)(Bs + (tx + 16) * 130 + kk);
            a00 = fmaf(x0.x, y0.x, a00); a00 = fmaf(x0.y, y0.y, a00);
            a01 = fmaf(x0.x, y1.x, a01); a01 = fmaf(x0.y, y1.y, a01);
            a10 = fmaf(x1.x, y0.x, a10); a10 = fmaf(x1.y, y0.y, a10);
            a11 = fmaf(x1.x, y1.x, a11); a11 = fmaf(x1.y, y1.y, a11);
        }
    }
    int i = i0 + ty, j = j0 + tx;
    // column 0 zeroed: the k-mask (t_k==0) is applied here once for all batches
    if (i < kV) {
        if (j < kV)      g_grams[i * kVP + j]      = j ? pack_split(a00) : 0u;
        if (j + 16 < kV) g_grams[i * kVP + j + 16] = pack_split(a01);
    }
    if (i + 16 < kV) {
        if (j < kV)      g_grams[(i + 16) * kVP + j]      = j ? pack_split(a10) : 0u;
        if (j + 16 < kV) g_grams[(i + 16) * kVP + j + 16] = pack_split(a11);
    }
}

// ---------------------------------------------------------------------------
// Kernel 3 (main): grid (1024, 2); CTA = (batch, 256-col half), 256 threads,
// 86.5 KB smem -> 2 CTAs/SM.
// ---------------------------------------------------------------------------
__global__ void __launch_bounds__(256, 2) main_kernel(
    const int* __restrict__ ids_en, const int* __restrict__ ids_fr,
    const float* __restrict__ emb, float* __restrict__ out) {
    extern __shared__ char smem[];
    const uint32_t sb = smem_u32(smem);
    int* tfr = (int*)(smem + OFF_TFR);
    int* ten = (int*)(smem + OFF_TEN);

    const int b = blockIdx.x;
    const int coff = blockIdx.y * kN;
    const int tid = threadIdx.x;
    const int lane = tid & 31, w = tid >> 5;

    if (tid < 64)       tfr[tid]      = ids_fr[b * 64 + tid];
    else if (tid < 128) ten[tid - 64] = ids_en[b * 64 + (tid - 64)];
    __syncthreads();

    // ---- Build S planes from G ROWS (coalesced), two 32-row passes ----------
    // G-row buffer aliases the full P hi+lo region (P staged afterwards).
    for (int h = 0; h < 2; h++) {
        // stage 32 G rows: warp w loads rows w, w+8, w+16, w+24 (uint4)
#pragma unroll
        for (int rr = 0; rr < 4; rr++) {
            int i = w + 8 * rr;
            const uint4* src = (const uint4*)(g_grams + (size_t)tfr[32 * h + i] * kVP);
            uint4* dst = (uint4*)(smem + OFF_PHI + i * GSTRB);
#pragma unroll
            for (int it = 0; it < 3; it++) {
                int c4 = lane + 32 * it;
                if (c4 < 76) dst[c4] = __ldg(src + c4);
            }
        }
        __syncthreads();
        // column-select -> S hi/lo planes (masking pre-baked: G col 0 == 0)
        for (int t4 = tid; t4 < 1024; t4 += 256) {
            int i = t4 >> 5, kp = t4 & 31;
            const uint32_t* grow = (const uint32_t*)(smem + OFF_PHI + i * GSTRB);
            uint32_t v0 = grow[tfr[2 * kp]];
            uint32_t v1 = grow[tfr[2 * kp + 1]];
            int q = 32 * h + i;
            *(uint32_t*)(smem + OFF_SHI + q * SROWB + kp * 4) = prmt(v0, v1, 0x7632);
            *(uint32_t*)(smem + OFF_SLO + q * SROWB + kp * 4) = prmt(v0, v1, 0x5410);
        }
        __syncthreads();
    }

    // ---- Stage P = proj[ids_fr] (256-col slice) as bf16 hi/lo planes --------
    for (int idx = tid; idx < 64 * 128; idx += 256) {
        int r = idx >> 7, dp = idx & 127;
        uint2 v = __ldg((const uint2*)(g_projs + (size_t)tfr[r] * kD + coff + dp * 2));
        *(uint32_t*)(smem + OFF_PHI + r * PROWB + dp * 4) = prmt(v.x, v.y, 0x7632);
        *(uint32_t*)(smem + OFF_PLO + r * PROWB + dp * 4) = prmt(v.x, v.y, 0x5410);
    }
    __syncthreads();

    // ---- Main GEMM: warp = (qh = w&1 -> 32 q-rows, seg = w>>1 -> 64 cols) ---
    const int qh = w & 1, seg = w >> 1;
    const uint32_t aS0 = sb + OFF_SHI
        + (uint32_t)(32 * qh + (lane & 15)) * SROWB + ((lane >> 4) * 16);
    const uint32_t aS1 = aS0 + 16 * SROWB;
    const uint32_t bT = sb + OFF_PHI + (uint32_t)(lane & 15) * PROWB
        + (uint32_t)(64 * seg + (lane >> 4) * 8) * 2;

    float acc[2][8][4];
#pragma unroll
    for (int mt = 0; mt < 2; mt++)
#pragma unroll
        for (int nt = 0; nt < 8; nt++)
#pragma unroll
            for (int i = 0; i < 4; i++) acc[mt][nt][i] = 0.f;

#pragma unroll
    for (int ks = 0; ks < 4; ks++) {
        uint32_t AH0[4], AH1[4], AL0[4], AL1[4];
        ldsm4(AH0, aS0 + ks * 32);
        ldsm4(AH1, aS1 + ks * 32);
        ldsm4(AL0, aS0 + DSL + ks * 32);
        ldsm4(AL1, aS1 + DSL + ks * 32);
#pragma unroll
        for (int nt = 0; nt < 4; nt++) {
            uint32_t adr = bT + (uint32_t)(ks * 16) * PROWB + nt * 32;
            uint32_t bH[4], bL[4];
            ldsm4t(bH, adr);
            ldsm4t(bL, adr + DPL);
            mma_bf16(acc[0][2 * nt],     AH0, bH);
            mma_bf16(acc[0][2 * nt],     AH0, bL);
            mma_bf16(acc[0][2 * nt],     AL0, bH);
            mma_bf16(acc[0][2 * nt + 1], AH0, bH + 2);
            mma_bf16(acc[0][2 * nt + 1], AH0, bL + 2);
            mma_bf16(acc[0][2 * nt + 1], AL0, bH + 2);
            mma_bf16(acc[1][2 * nt],     AH1, bH);
            mma_bf16(acc[1][2 * nt],     AH1, bL);
            mma_bf16(acc[1][2 * nt],     AL1, bH);
            mma_bf16(acc[1][2 * nt + 1], AH1, bH + 2);
            mma_bf16(acc[1][2 * nt + 1], AH1, bL + 2);
            mma_bf16(acc[1][2 * nt + 1], AL1, bH + 2);
        }
    }

    // ---- Epilogue: out = enc + emb[ids_en] ----------------------------------
    const int cb = coff + 64 * seg + 2 * (lane & 3);
#pragma unroll
    for (int mt = 0; mt < 2; mt++) {
        int ra = 32 * qh + 16 * mt + (lane >> 2);
        int rb = ra + 8;
        const float* ea = emb + (size_t)ten[ra] * kD + cb;
        const float* eb = emb + (size_t)ten[rb] * kD + cb;
        float* oa = out + ((size_t)b * 64 + ra) * kD + cb;
        float* ob = out + ((size_t)b * 64 + rb) * kD + cb;
#pragma unroll
        for (int nt = 0; nt < 8; nt++) {
            float2 ga = __ldg((const float2*)(ea + nt * 8));
            float2 gb = __ldg((const float2*)(eb + nt * 8));
            *(float2*)(oa + nt * 8) =
                make_float2(acc[mt][nt][0] + ga.x, acc[mt][nt][1] + ga.y);
            *(float2*)(ob + nt * 8) =
                make_float2(acc[mt][nt][2] + gb.x, acc[mt][nt][3] + gb.y);
        }
    }
}

// ---------------------------------------------------------------------------
extern "C" void kernel_launch(void* const* d_in, const int* in_sizes, int n_in,
                              void* d_out, int out_size) {
    (void)in_sizes; (void)n_in; (void)out_size;
    const int* ids_en = (const int*)d_in[0];
    const int* ids_fr = (const int*)d_in[1];
    const float* emb  = (const float*)d_in[2];
    const float* Wq   = (const float*)d_in[3];
    float* out        = (float*)d_out;

    proj_kernel<<<dim3(19, 16), 256>>>(emb, Wq);
    gram_kernel<<<dim3(10, 10), 256>>>();
    cudaFuncSetAttribute(main_kernel, cudaFuncAttributeMaxDynamicSharedMemorySize,
                         SMEM_MAIN);
    main_kernel<<<dim3(kB, 2), 256, SMEM_MAIN>>>(ids_en, ids_fr, emb, out);
}

// round 11
// speedup vs baseline: 1.2378x; 1.1477x over previous
#include <cuda_runtime.h>
#include <cuda_bf16.h>
#include <cstdint>

// ---------------------------------------------------------------------------
// out = emb[ids_en] + S @ V,  vocab collapse:
//   proj = emb @ Qdense [300,512] -> fp32 g_proj + packed bf16 {hi|lo} g_projs
//   G = proj projT -> packed g_grams (stride 304, col 0 zeroed == k-mask)
//   sbuild (per batch): gather 64 G rows coalesced, column-select -> packed
//     S hi/lo planes in global g_sp (16.8 MB, L2-resident)
//   main (per batch x 4 column-CTAs, 3 CTAs/SM): load S planes + P slice,
//     enc = S @ V via mma.sync bf16 3-product split, out = enc + emb[ids_en]
// (tcgen05 unavailable: harness builds through plain compute_103 PTX.)
// ---------------------------------------------------------------------------

namespace {
constexpr int kB = 1024;
constexpr int kV = 300;
constexpr int kVP = 304;      // g_grams row stride (words)
constexpr int kD = 512;
constexpr int kN = 128;       // cols per main CTA (batch split in 4)

// sbuild smem
constexpr int GSTRB = 1216;                      // G row bytes (304 words)
constexpr int SB_TFR = 64 * GSTRB;               // 77,824
constexpr int SMEM_SB = SB_TFR + 256;            // 78,080 -> 2 CTAs/SM

// main smem
constexpr int PROW2 = 272;                       // P plane row stride (128 bf16 + 16B)
constexpr int SROWB = 144;                       // S plane row stride (64 bf16 + 16B)
constexpr int OFF_PHI = 0;
constexpr int OFF_PLO = 64 * PROW2;              // 17,408
constexpr int DPL2    = OFF_PLO - OFF_PHI;
constexpr int OFF_SHI = 2 * 64 * PROW2;          // 34,816
constexpr int OFF_SLO = OFF_SHI + 64 * SROWB;    // 44,032
constexpr int DSL     = OFF_SLO - OFF_SHI;
constexpr int OFF_TFR = OFF_SLO + 64 * SROWB;    // 53,248
constexpr int OFF_TEN = OFF_TFR + 256;
constexpr int SMEM_MAIN = OFF_TEN + 256;         // 53,760 -> 3 CTAs/SM (regs)
}

__device__ float    g_proj [kV * kD];        // fp32 proj (gram input)
__device__ uint32_t g_projs[kV * kD];        // packed {bf16 hi | bf16 lo}
__device__ uint32_t g_grams[kV * kVP];       // packed gram, col 0 zeroed
__device__ uint32_t g_sp   [kB * 4096];      // per-batch S planes: [b][2][64][32]

// ---------------- helpers --------------------------------------------------
__device__ __forceinline__ uint32_t smem_u32(const void* p) {
    uint32_t a;
    asm("{ .reg .u64 t; cvta.to.shared.u64 t, %1; cvt.u32.u64 %0, t; }"
        : "=r"(a) : "l"(p));
    return a;
}
__device__ __forceinline__ uint32_t prmt(uint32_t a, uint32_t b, uint32_t sel) {
    uint32_t d;
    asm("prmt.b32 %0, %1, %2, %3;" : "=r"(d) : "r"(a), "r"(b), "r"(sel));
    return d;
}
__device__ __forceinline__ void ldsm4(uint32_t* r, uint32_t addr) {
    asm volatile("ldmatrix.sync.aligned.m8n8.x4.shared.b16 {%0,%1,%2,%3}, [%4];"
                 : "=r"(r[0]), "=r"(r[1]), "=r"(r[2]), "=r"(r[3]) : "r"(addr));
}
__device__ __forceinline__ void ldsm4t(uint32_t* r, uint32_t addr) {
    asm volatile("ldmatrix.sync.aligned.m8n8.x4.trans.shared.b16 {%0,%1,%2,%3}, [%4];"
                 : "=r"(r[0]), "=r"(r[1]), "=r"(r[2]), "=r"(r[3]) : "r"(addr));
}
__device__ __forceinline__ void mma_bf16(float* c, const uint32_t* a,
                                         const uint32_t* b) {
    asm volatile(
        "mma.sync.aligned.m16n8k16.row.col.f32.bf16.bf16.f32 "
        "{%0,%1,%2,%3}, {%4,%5,%6,%7}, {%8,%9}, {%0,%1,%2,%3};"
        : "+f"(c[0]), "+f"(c[1]), "+f"(c[2]), "+f"(c[3])
        : "r"(a[0]), "r"(a[1]), "r"(a[2]), "r"(a[3]), "r"(b[0]), "r"(b[1]));
}
__device__ __forceinline__ uint32_t pack_split(float v) {
    __nv_bfloat16 h = __float2bfloat16(v);
    float hf = __bfloat162float(h);
    __nv_bfloat16 l = __float2bfloat16(v - hf);
    return ((uint32_t)__bfloat16_as_ushort(h) << 16) | __bfloat16_as_ushort(l);
}

// ---------------------------------------------------------------------------
// Kernel 1: proj = emb @ Qdense -> g_proj fp32 + g_projs packed. (validated)
// ---------------------------------------------------------------------------
__global__ void __launch_bounds__(256) proj_kernel(const float* __restrict__ emb,
                                                   const float* __restrict__ Wq) {
    __shared__ float As[16 * 65];
    __shared__ float Bs[64 * 36];
    const int r0 = blockIdx.x * 16, c0 = blockIdx.y * 32;
    const int t = threadIdx.x;
    const int r = t & 15, cg = t >> 4;
    float2 acc = make_float2(0.f, 0.f);

    for (int kc = 0; kc < kD; kc += 64) {
        __syncthreads();
        {
            int ar = t >> 4, ak4 = t & 15;
            float4 v = make_float4(0.f, 0.f, 0.f, 0.f);
            if (r0 + ar < kV) v = *(const float4*)(emb + (r0 + ar) * kD + kc + ak4 * 4);
            float* d = As + ar * 65 + ak4 * 4;
            d[0] = v.x; d[1] = v.y; d[2] = v.z; d[3] = v.w;
        }
        {
            int c4 = t & 7;
#pragma unroll
            for (int j = 0; j < 2; j++) {
                int bk = (t >> 3) + 32 * j;
                float4 v = *(const float4*)(Wq + (kc + bk) * kD + c0 + c4 * 4);
                *(float4*)(Bs + bk * 36 + c4 * 4) = v;
            }
        }
        __syncthreads();
#pragma unroll 8
        for (int kk = 0; kk < 64; kk++) {
            float a = As[r * 65 + kk];
            float2 bv = *(const float2*)(Bs + kk * 36 + cg * 2);
            acc.x = fmaf(a, bv.x, acc.x);
            acc.y = fmaf(a, bv.y, acc.y);
        }
    }
    if (r0 + r < kV) {
        int idx = (r0 + r) * kD + c0 + cg * 2;
        *(float2*)(g_proj + idx) = acc;
        g_projs[idx]     = pack_split(acc.x);
        g_projs[idx + 1] = pack_split(acc.y);
    }
}

// ---------------------------------------------------------------------------
// Kernel 2: G = proj projT -> packed g_grams, col 0 zeroed. (validated)
// ---------------------------------------------------------------------------
__global__ void __launch_bounds__(256) gram_kernel() {
    __shared__ float As[32 * 130];
    __shared__ float Bs[32 * 130];
    const int i0 = blockIdx.x * 32, j0 = blockIdx.y * 32;
    const int t = threadIdx.x;
    const int tx = t & 15, ty = t >> 4;
    float a00 = 0.f, a01 = 0.f, a10 = 0.f, a11 = 0.f;

    for (int kc = 0; kc < kD; kc += 128) {
        __syncthreads();
        {
            int sr = t >> 3;
#pragma unroll
            for (int j = 0; j < 4; j++) {
                int c4 = (t & 7) + 8 * j;
                float4 va = make_float4(0.f, 0.f, 0.f, 0.f);
                float4 vb = make_float4(0.f, 0.f, 0.f, 0.f);
                if (i0 + sr < kV) va = *(const float4*)(g_proj + (i0 + sr) * kD + kc + c4 * 4);
                if (j0 + sr < kV) vb = *(const float4*)(g_proj + (j0 + sr) * kD + kc + c4 * 4);
                float2* da = (float2*)(As + sr * 130 + c4 * 4);
                float2* db = (float2*)(Bs + sr * 130 + c4 * 4);
                da[0] = make_float2(va.x, va.y); da[1] = make_float2(va.z, va.w);
                db[0] = make_float2(vb.x, vb.y); db[1] = make_float2(vb.z, vb.w);
            }
        }
        __syncthreads();
#pragma unroll 8
        for (int kk = 0; kk < 128; kk += 2) {
            float2 x0 = *(const float2*)(As + ty * 130 + kk);
            float2 x1 = *(const float2*)(As + (ty + 16) * 130 + kk);
            float2 y0 = *(const float2*)(Bs + tx * 130 + kk);
            float2 y1 = *(const float2*)(Bs + (tx + 16) * 130 + kk);
            a00 = fmaf(x0.x, y0.x, a00); a00 = fmaf(x0.y, y0.y, a00);
            a01 = fmaf(x0.x, y1.x, a01); a01 = fmaf(x0.y, y1.y, a01);
            a10 = fmaf(x1.x, y0.x, a10); a10 = fmaf(x1.y, y0.y, a10);
            a11 = fmaf(x1.x, y1.x, a11); a11 = fmaf(x1.y, y1.y, a11);
        }
    }
    int i = i0 + ty, j = j0 + tx;
    if (i < kV) {
        if (j < kV)      g_grams[i * kVP + j]      = j ? pack_split(a00) : 0u;
        if (j + 16 < kV) g_grams[i * kVP + j + 16] = pack_split(a01);
    }
    if (i + 16 < kV) {
        if (j < kV)      g_grams[(i + 16) * kVP + j]      = j ? pack_split(a10) : 0u;
        if (j + 16 < kV) g_grams[(i + 16) * kVP + j + 16] = pack_split(a11);
    }
}

// ---------------------------------------------------------------------------
// Kernel 3 (sbuild): one CTA per batch; gather the 64 needed G ROWS coalesced,
// column-select -> packed S hi/lo planes g_sp[b][2][64][32]. Mask pre-baked.
// ---------------------------------------------------------------------------
__global__ void __launch_bounds__(256) sbuild_kernel(const int* __restrict__ ids_fr) {
    extern __shared__ char smem[];
    int* tfr = (int*)(smem + SB_TFR);
    const int b = blockIdx.x;
    const int tid = threadIdx.x;

    if (tid < 64) tfr[tid] = ids_fr[b * 64 + tid];
    __syncthreads();

    // stage 64 G rows (76 uint4 each = 4864 tasks = 19 per thread)
    for (int idx = tid; idx < 64 * 76; idx += 256) {
        int r = idx / 76, c = idx - r * 76;
        ((uint4*)(smem + r * GSTRB))[c] =
            __ldg((const uint4*)(g_grams + (size_t)tfr[r] * kVP) + c);
    }
    __syncthreads();

    // column-select + pack: task (q, kp); stores coalesced per warp
    uint32_t* sp = g_sp + ((size_t)b << 12);
    for (int t4 = tid; t4 < 2048; t4 += 256) {
        int q = t4 >> 5, kp = t4 & 31;
        const uint32_t* grow = (const uint32_t*)(smem + q * GSTRB);
        uint32_t v0 = grow[tfr[2 * kp]];
        uint32_t v1 = grow[tfr[2 * kp + 1]];
        sp[(q << 5) + kp]        = prmt(v0, v1, 0x7632);   // hi plane
        sp[2048 + (q << 5) + kp] = prmt(v0, v1, 0x5410);   // lo plane
    }
}

// ---------------------------------------------------------------------------
// Kernel 4 (main): grid (1024, 4); CTA = (batch, 128-col quarter), 256 thr,
// 53.8 KB smem, <=85 regs -> 3 CTAs/SM. Warp w: q-tile (w&3)*16, n-half
// (w>>2)*64. enc = S @ V (3-product bf16), out = enc + emb[ids_en].
// ---------------------------------------------------------------------------
__global__ void __launch_bounds__(256, 3) main_kernel(
    const int* __restrict__ ids_en, const int* __restrict__ ids_fr,
    const float* __restrict__ emb, float* __restrict__ out) {
    extern __shared__ char smem[];
    const uint32_t sb = smem_u32(smem);
    int* tfr = (int*)(smem + OFF_TFR);
    int* ten = (int*)(smem + OFF_TEN);

    const int b = blockIdx.x;
    const int coff = blockIdx.y * kN;            // fp32 column offset
    const int tid = threadIdx.x;
    const int lane = tid & 31, w = tid >> 5;

    if (tid < 64)       tfr[tid]      = ids_fr[b * 64 + tid];
    else if (tid < 128) ten[tid - 64] = ids_en[b * 64 + (tid - 64)];
    __syncthreads();

    // ---- Load S planes (coalesced uint4): 1024 tasks, 4 per thread ----------
    {
        const uint4* sp = (const uint4*)(g_sp + ((size_t)b << 12));
#pragma unroll
        for (int i = 0; i < 4; i++) {
            int idx = tid + 256 * i;
            uint4 v = __ldg(sp + idx);
            int w4 = idx * 4;
            int p = w4 >> 11, rem = w4 & 2047;
            int q = rem >> 5, k0 = rem & 31;
            *(uint4*)(smem + (p ? OFF_SLO : OFF_SHI) + q * SROWB + k0 * 4) = v;
        }
    }
    // ---- Stage P slice (64 x 128 cols) as hi/lo planes: 2048 uint4 tasks ----
#pragma unroll
    for (int i = 0; i < 8; i++) {
        int idx = tid + 256 * i;
        int r = idx >> 5, g = idx & 31;          // row, uint4 col-group (4 cols)
        uint4 v = __ldg((const uint4*)(g_projs + (size_t)tfr[r] * kD + coff) + g);
        uint2 hi = make_uint2(prmt(v.x, v.y, 0x7632), prmt(v.z, v.w, 0x7632));
        uint2 lo = make_uint2(prmt(v.x, v.y, 0x5410), prmt(v.z, v.w, 0x5410));
        *(uint2*)(smem + OFF_PHI + r * PROW2 + g * 8) = hi;
        *(uint2*)(smem + OFF_PLO + r * PROW2 + g * 8) = lo;
    }
    __syncthreads();

    // ---- MMA: warp tile 16q x 64n ------------------------------------------
    const int qt = w & 3, nh = w >> 2;
    const uint32_t aS = sb + OFF_SHI
        + (uint32_t)(16 * qt + (lane & 15)) * SROWB + ((lane >> 4) * 16);
    const uint32_t bT = sb + OFF_PHI + (uint32_t)(lane & 15) * PROW2
        + (uint32_t)(64 * nh + (lane >> 4) * 8) * 2;

    float acc[8][4];
#pragma unroll
    for (int nt = 0; nt < 8; nt++)
#pragma unroll
        for (int i = 0; i < 4; i++) acc[nt][i] = 0.f;

#pragma unroll
    for (int ks = 0; ks < 4; ks++) {
        uint32_t AH[4], AL[4];
        ldsm4(AH, aS + ks * 32);
        ldsm4(AL, aS + DSL + ks * 32);
#pragma unroll
        for (int p = 0; p < 4; p++) {
            uint32_t adr = bT + (uint32_t)(ks * 16) * PROW2 + p * 32;
            uint32_t bH[4], bL[4];
            ldsm4t(bH, adr);
            ldsm4t(bL, adr + DPL2);
            mma_bf16(acc[2 * p],     AH, bH);
            mma_bf16(acc[2 * p],     AH, bL);
            mma_bf16(acc[2 * p],     AL, bH);
            mma_bf16(acc[2 * p + 1], AH, bH + 2);
            mma_bf16(acc[2 * p + 1], AH, bL + 2);
            mma_bf16(acc[2 * p + 1], AL, bH + 2);
        }
    }

    // ---- Epilogue: out = enc + emb[ids_en] ----------------------------------
    const int ra = 16 * qt + (lane >> 2), rb = ra + 8;
    const int cb = coff + 64 * nh + 2 * (lane & 3);
    const float* ea = emb + (size_t)ten[ra] * kD + cb;
    const float* eb = emb + (size_t)ten[rb] * kD + cb;
    float* oa = out + ((size_t)b * 64 + ra) * kD + cb;
    float* ob = out + ((size_t)b * 64 + rb) * kD + cb;
#pragma unroll
    for (int nt = 0; nt < 8; nt++) {
        float2 ga = __ldg((const float2*)(ea + nt * 8));
        float2 gb = __ldg((const float2*)(eb + nt * 8));
        *(float2*)(oa + nt * 8) = make_float2(acc[nt][0] + ga.x, acc[nt][1] + ga.y);
        *(float2*)(ob + nt * 8) = make_float2(acc[nt][2] + gb.x, acc[nt][3] + gb.y);
    }
}

// ---------------------------------------------------------------------------
extern "C" void kernel_launch(void* const* d_in, const int* in_sizes, int n_in,
                              void* d_out, int out_size) {
    (void)in_sizes; (void)n_in; (void)out_size;
    const int* ids_en = (const int*)d_in[0];
    const int* ids_fr = (const int*)d_in[1];
    const float* emb  = (const float*)d_in[2];
    const float* Wq   = (const float*)d_in[3];
    float* out        = (float*)d_out;

    proj_kernel<<<dim3(19, 16), 256>>>(emb, Wq);
    gram_kernel<<<dim3(10, 10), 256>>>();
    cudaFuncSetAttribute(sbuild_kernel, cudaFuncAttributeMaxDynamicSharedMemorySize,
                         SMEM_SB);
    sbuild_kernel<<<kB, 256, SMEM_SB>>>(ids_fr);
    cudaFuncSetAttribute(main_kernel, cudaFuncAttributeMaxDynamicSharedMemorySize,
                         SMEM_MAIN);
    main_kernel<<<dim3(kB, 4), 256, SMEM_MAIN>>>(ids_en, ids_fr, emb, out);
}

// round 12
// speedup vs baseline: 1.3536x; 1.0935x over previous
#include <cuda_runtime.h>
#include <cuda_bf16.h>
#include <cstdint>

// ---------------------------------------------------------------------------
// out = emb[ids_en] + S @ V,  vocab collapse:
//   proj = emb @ Qdense [300,512] -> fp32 g_proj + packed bf16 {hi|lo} g_projs
//   G = proj projT -> packed g_grams (stride 304, col 0 zeroed == k-mask)
//   sbuild (per batch x 2 CTAs): gather 32 G rows coalesced each,
//     column-select -> packed S hi/lo planes in global g_sp (L2-resident)
//   main (per batch x 4 column-CTAs, 3 CTAs/SM): load S planes + P slice,
//     enc = S @ V via mma.sync bf16 3-product split (32x32 warp tiles),
//     out = enc + emb[ids_en]
// (tcgen05 unavailable: harness builds through plain compute_103 PTX.)
// ---------------------------------------------------------------------------

namespace {
constexpr int kB = 1024;
constexpr int kV = 300;
constexpr int kVP = 304;      // g_grams row stride (words)
constexpr int kD = 512;
constexpr int kN = 128;       // cols per main CTA (batch split in 4)

// sbuild smem (32 G rows per CTA)
constexpr int GSTRB = 1216;                      // G row bytes (304 words)
constexpr int SB_TFR = 32 * GSTRB;               // 38,912
constexpr int SMEM_SB = SB_TFR + 256;            // 39,168 -> 5 CTAs/SM

// main smem
constexpr int PROW2 = 272;                       // P plane row stride (128 bf16 + 16B)
constexpr int SROWB = 144;                       // S plane row stride (64 bf16 + 16B)
constexpr int OFF_PHI = 0;
constexpr int OFF_PLO = 64 * PROW2;              // 17,408
constexpr int DPL2    = OFF_PLO - OFF_PHI;
constexpr int OFF_SHI = 2 * 64 * PROW2;          // 34,816
constexpr int OFF_SLO = OFF_SHI + 64 * SROWB;    // 44,032
constexpr int DSL     = OFF_SLO - OFF_SHI;
constexpr int OFF_TFR = OFF_SLO + 64 * SROWB;    // 53,248
constexpr int OFF_TEN = OFF_TFR + 256;
constexpr int SMEM_MAIN = OFF_TEN + 256;         // 53,760 -> 3 CTAs/SM (regs)
}

__device__ float    g_proj [kV * kD];        // fp32 proj (gram input)
__device__ uint32_t g_projs[kV * kD];        // packed {bf16 hi | bf16 lo}
__device__ uint32_t g_grams[kV * kVP];       // packed gram, col 0 zeroed
__device__ uint32_t g_sp   [kB * 4096];      // per-batch S planes: [b][2][64][32]

// ---------------- helpers --------------------------------------------------
__device__ __forceinline__ uint32_t smem_u32(const void* p) {
    uint32_t a;
    asm("{ .reg .u64 t; cvta.to.shared.u64 t, %1; cvt.u32.u64 %0, t; }"
        : "=r"(a) : "l"(p));
    return a;
}
__device__ __forceinline__ uint32_t prmt(uint32_t a, uint32_t b, uint32_t sel) {
    uint32_t d;
    asm("prmt.b32 %0, %1, %2, %3;" : "=r"(d) : "r"(a), "r"(b), "r"(sel));
    return d;
}
__device__ __forceinline__ void ldsm4(uint32_t* r, uint32_t addr) {
    asm volatile("ldmatrix.sync.aligned.m8n8.x4.shared.b16 {%0,%1,%2,%3}, [%4];"
                 : "=r"(r[0]), "=r"(r[1]), "=r"(r[2]), "=r"(r[3]) : "r"(addr));
}
__device__ __forceinline__ void ldsm4t(uint32_t* r, uint32_t addr) {
    asm volatile("ldmatrix.sync.aligned.m8n8.x4.trans.shared.b16 {%0,%1,%2,%3}, [%4];"
                 : "=r"(r[0]), "=r"(r[1]), "=r"(r[2]), "=r"(r[3]) : "r"(addr));
}
__device__ __forceinline__ void mma_bf16(float* c, const uint32_t* a,
                                         const uint32_t* b) {
    asm volatile(
        "mma.sync.aligned.m16n8k16.row.col.f32.bf16.bf16.f32 "
        "{%0,%1,%2,%3}, {%4,%5,%6,%7}, {%8,%9}, {%0,%1,%2,%3};"
        : "+f"(c[0]), "+f"(c[1]), "+f"(c[2]), "+f"(c[3])
        : "r"(a[0]), "r"(a[1]), "r"(a[2]), "r"(a[3]), "r"(b[0]), "r"(b[1]));
}
__device__ __forceinline__ uint32_t pack_split(float v) {
    __nv_bfloat16 h = __float2bfloat16(v);
    float hf = __bfloat162float(h);
    __nv_bfloat16 l = __float2bfloat16(v - hf);
    return ((uint32_t)__bfloat16_as_ushort(h) << 16) | __bfloat16_as_ushort(l);
}

// ---------------------------------------------------------------------------
// Kernel 1: proj = emb @ Qdense -> g_proj fp32 + g_projs packed. (validated)
// ---------------------------------------------------------------------------
__global__ void __launch_bounds__(256) proj_kernel(const float* __restrict__ emb,
                                                   const float* __restrict__ Wq) {
    __shared__ float As[16 * 65];
    __shared__ float Bs[64 * 36];
    const int r0 = blockIdx.x * 16, c0 = blockIdx.y * 32;
    const int t = threadIdx.x;
    const int r = t & 15, cg = t >> 4;
    float2 acc = make_float2(0.f, 0.f);

    for (int kc = 0; kc < kD; kc += 64) {
        __syncthreads();
        {
            int ar = t >> 4, ak4 = t & 15;
            float4 v = make_float4(0.f, 0.f, 0.f, 0.f);
            if (r0 + ar < kV) v = *(const float4*)(emb + (r0 + ar) * kD + kc + ak4 * 4);
            float* d = As + ar * 65 + ak4 * 4;
            d[0] = v.x; d[1] = v.y; d[2] = v.z; d[3] = v.w;
        }
        {
            int c4 = t & 7;
#pragma unroll
            for (int j = 0; j < 2; j++) {
                int bk = (t >> 3) + 32 * j;
                float4 v = *(const float4*)(Wq + (kc + bk) * kD + c0 + c4 * 4);
                *(float4*)(Bs + bk * 36 + c4 * 4) = v;
            }
        }
        __syncthreads();
#pragma unroll 8
        for (int kk = 0; kk < 64; kk++) {
            float a = As[r * 65 + kk];
            float2 bv = *(const float2*)(Bs + kk * 36 + cg * 2);
            acc.x = fmaf(a, bv.x, acc.x);
            acc.y = fmaf(a, bv.y, acc.y);
        }
    }
    if (r0 + r < kV) {
        int idx = (r0 + r) * kD + c0 + cg * 2;
        *(float2*)(g_proj + idx) = acc;
        g_projs[idx]     = pack_split(acc.x);
        g_projs[idx + 1] = pack_split(acc.y);
    }
}

// ---------------------------------------------------------------------------
// Kernel 2: G = proj projT -> packed g_grams, col 0 zeroed. (validated)
// ---------------------------------------------------------------------------
__global__ void __launch_bounds__(256) gram_kernel() {
    __shared__ float As[32 * 130];
    __shared__ float Bs[32 * 130];
    const int i0 = blockIdx.x * 32, j0 = blockIdx.y * 32;
    const int t = threadIdx.x;
    const int tx = t & 15, ty = t >> 4;
    float a00 = 0.f, a01 = 0.f, a10 = 0.f, a11 = 0.f;

    for (int kc = 0; kc < kD; kc += 128) {
        __syncthreads();
        {
            int sr = t >> 3;
#pragma unroll
            for (int j = 0; j < 4; j++) {
                int c4 = (t & 7) + 8 * j;
                float4 va = make_float4(0.f, 0.f, 0.f, 0.f);
                float4 vb = make_float4(0.f, 0.f, 0.f, 0.f);
                if (i0 + sr < kV) va = *(const float4*)(g_proj + (i0 + sr) * kD + kc + c4 * 4);
                if (j0 + sr < kV) vb = *(const float4*)(g_proj + (j0 + sr) * kD + kc + c4 * 4);
                float2* da = (float2*)(As + sr * 130 + c4 * 4);
                float2* db = (float2*)(Bs + sr * 130 + c4 * 4);
                da[0] = make_float2(va.x, va.y); da[1] = make_float2(va.z, va.w);
                db[0] = make_float2(vb.x, vb.y); db[1] = make_float2(vb.z, vb.w);
            }
        }
        __syncthreads();
#pragma unroll 8
        for (int kk = 0; kk < 128; kk += 2) {
            float2 x0 = *(const float2*)(As + ty * 130 + kk);
            float2 x1 = *(const float2*)(As + (ty + 16) * 130 + kk);
            float2 y0 = *(const float2*)(Bs + tx * 130 + kk);
            float2 y1 = *(const float2*)(Bs + (tx + 16) * 130 + kk);
            a00 = fmaf(x0.x, y0.x, a00); a00 = fmaf(x0.y, y0.y, a00);
            a01 = fmaf(x0.x, y1.x, a01); a01 = fmaf(x0.y, y1.y, a01);
            a10 = fmaf(x1.x, y0.x, a10); a10 = fmaf(x1.y, y0.y, a10);
            a11 = fmaf(x1.x, y1.x, a11); a11 = fmaf(x1.y, y1.y, a11);
        }
    }
    int i = i0 + ty, j = j0 + tx;
    if (i < kV) {
        if (j < kV)      g_grams[i * kVP + j]      = j ? pack_split(a00) : 0u;
        if (j + 16 < kV) g_grams[i * kVP + j + 16] = pack_split(a01);
    }
    if (i + 16 < kV) {
        if (j < kV)      g_grams[(i + 16) * kVP + j]      = j ? pack_split(a10) : 0u;
        if (j + 16 < kV) g_grams[(i + 16) * kVP + j + 16] = pack_split(a11);
    }
}

// ---------------------------------------------------------------------------
// Kernel 3 (sbuild): grid (1024, 2); CTA = (batch, 32-q-row half).
// Stage 32 G rows coalesced (39 KB smem -> 5 CTAs/SM), column-select ->
// packed S hi/lo planes g_sp[b][2][64][32]. Mask pre-baked (G col 0 == 0).
// ---------------------------------------------------------------------------
__global__ void __launch_bounds__(256) sbuild_kernel(const int* __restrict__ ids_fr) {
    extern __shared__ char smem[];
    int* tfr = (int*)(smem + SB_TFR);
    const int b = blockIdx.x;
    const int h = blockIdx.y;
    const int tid = threadIdx.x;

    if (tid < 64) tfr[tid] = ids_fr[b * 64 + tid];
    __syncthreads();

    // stage 32 G rows (76 uint4 each = 2432 tasks)
    for (int idx = tid; idx < 32 * 76; idx += 256) {
        int r = idx / 76, c = idx - r * 76;
        ((uint4*)(smem + r * GSTRB))[c] =
            __ldg((const uint4*)(g_grams + (size_t)tfr[32 * h + r] * kVP) + c);
    }
    __syncthreads();

    // column-select + pack: task (i, kp); stores coalesced per warp
    uint32_t* sp = g_sp + ((size_t)b << 12);
    for (int t4 = tid; t4 < 1024; t4 += 256) {
        int i = t4 >> 5, kp = t4 & 31;
        int q = 32 * h + i;
        const uint32_t* grow = (const uint32_t*)(smem + i * GSTRB);
        uint32_t v0 = grow[tfr[2 * kp]];
        uint32_t v1 = grow[tfr[2 * kp + 1]];
        sp[(q << 5) + kp]        = prmt(v0, v1, 0x7632);   // hi plane
        sp[2048 + (q << 5) + kp] = prmt(v0, v1, 0x5410);   // lo plane
    }
}

// ---------------------------------------------------------------------------
// Kernel 4 (main): grid (1024, 4); CTA = (batch, 128-col quarter), 256 thr,
// 53.8 KB smem, ~80 regs -> 3 CTAs/SM. Warp tile 32q x 32n (warps 2m x 4n):
// ldsm per k-sweep 32/warp (vs 40 at 16x64). enc = S @ V (3-product bf16),
// out = enc + emb[ids_en].
// ---------------------------------------------------------------------------
__global__ void __launch_bounds__(256, 3) main_kernel(
    const int* __restrict__ ids_en, const int* __restrict__ ids_fr,
    const float* __restrict__ emb, float* __restrict__ out) {
    extern __shared__ char smem[];
    const uint32_t sb = smem_u32(smem);
    int* tfr = (int*)(smem + OFF_TFR);
    int* ten = (int*)(smem + OFF_TEN);

    const int b = blockIdx.x;
    const int coff = blockIdx.y * kN;            // fp32 column offset
    const int tid = threadIdx.x;
    const int lane = tid & 31, w = tid >> 5;

    if (tid < 64)       tfr[tid]      = ids_fr[b * 64 + tid];
    else if (tid < 128) ten[tid - 64] = ids_en[b * 64 + (tid - 64)];
    __syncthreads();

    // ---- Load S planes (coalesced uint4): 1024 tasks, 4 per thread ----------
    {
        const uint4* sp = (const uint4*)(g_sp + ((size_t)b << 12));
#pragma unroll
        for (int i = 0; i < 4; i++) {
            int idx = tid + 256 * i;
            uint4 v = __ldg(sp + idx);
            int w4 = idx * 4;
            int p = w4 >> 11, rem = w4 & 2047;
            int q = rem >> 5, k0 = rem & 31;
            *(uint4*)(smem + (p ? OFF_SLO : OFF_SHI) + q * SROWB + k0 * 4) = v;
        }
    }
    // ---- Stage P slice (64 x 128 cols) as hi/lo planes: 2048 uint4 tasks ----
#pragma unroll
    for (int i = 0; i < 8; i++) {
        int idx = tid + 256 * i;
        int r = idx >> 5, g = idx & 31;          // row, uint4 col-group (4 cols)
        uint4 v = __ldg((const uint4*)(g_projs + (size_t)tfr[r] * kD + coff) + g);
        uint2 hi = make_uint2(prmt(v.x, v.y, 0x7632), prmt(v.z, v.w, 0x7632));
        uint2 lo = make_uint2(prmt(v.x, v.y, 0x5410), prmt(v.z, v.w, 0x5410));
        *(uint2*)(smem + OFF_PHI + r * PROW2 + g * 8) = hi;
        *(uint2*)(smem + OFF_PLO + r * PROW2 + g * 8) = lo;
    }
    __syncthreads();

    // ---- MMA: warp tile 32q x 32n (warps: mw = w&1, nw = w>>1) -------------
    const int mw = w & 1, nw = w >> 1;
    const uint32_t aS = sb + OFF_SHI
        + (uint32_t)(32 * mw + (lane & 15)) * SROWB + ((lane >> 4) * 16);
    const uint32_t bT = sb + OFF_PHI + (uint32_t)(lane & 15) * PROW2
        + (uint32_t)(32 * nw + (lane >> 4) * 8) * 2;

    float acc[2][4][4];
#pragma unroll
    for (int m = 0; m < 2; m++)
#pragma unroll
        for (int nt = 0; nt < 4; nt++)
#pragma unroll
            for (int i = 0; i < 4; i++) acc[m][nt][i] = 0.f;

#pragma unroll
    for (int ks = 0; ks < 4; ks++) {
        uint32_t AH0[4], AH1[4], AL0[4], AL1[4];
        ldsm4(AH0, aS + ks * 32);
        ldsm4(AH1, aS + 16 * SROWB + ks * 32);
        ldsm4(AL0, aS + DSL + ks * 32);
        ldsm4(AL1, aS + DSL + 16 * SROWB + ks * 32);
        uint32_t adr = bT + (uint32_t)(ks * 16) * PROW2;
        uint32_t bH0[4], bH1[4], bL0[4], bL1[4];
        ldsm4t(bH0, adr);
        ldsm4t(bH1, adr + 32);
        ldsm4t(bL0, adr + DPL2);
        ldsm4t(bL1, adr + DPL2 + 32);

        mma_bf16(acc[0][0], AH0, bH0);     mma_bf16(acc[0][0], AH0, bL0);
        mma_bf16(acc[0][0], AL0, bH0);
        mma_bf16(acc[0][1], AH0, bH0 + 2); mma_bf16(acc[0][1], AH0, bL0 + 2);
        mma_bf16(acc[0][1], AL0, bH0 + 2);
        mma_bf16(acc[0][2], AH0, bH1);     mma_bf16(acc[0][2], AH0, bL1);
        mma_bf16(acc[0][2], AL0, bH1);
        mma_bf16(acc[0][3], AH0, bH1 + 2); mma_bf16(acc[0][3], AH0, bL1 + 2);
        mma_bf16(acc[0][3], AL0, bH1 + 2);

        mma_bf16(acc[1][0], AH1, bH0);     mma_bf16(acc[1][0], AH1, bL0);
        mma_bf16(acc[1][0], AL1, bH0);
        mma_bf16(acc[1][1], AH1, bH0 + 2); mma_bf16(acc[1][1], AH1, bL0 + 2);
        mma_bf16(acc[1][1], AL1, bH0 + 2);
        mma_bf16(acc[1][2], AH1, bH1);     mma_bf16(acc[1][2], AH1, bL1);
        mma_bf16(acc[1][2], AL1, bH1);
        mma_bf16(acc[1][3], AH1, bH1 + 2); mma_bf16(acc[1][3], AH1, bL1 + 2);
        mma_bf16(acc[1][3], AL1, bH1 + 2);
    }

    // ---- Epilogue: out = enc + emb[ids_en] ----------------------------------
    const int cb = coff + 32 * nw + 2 * (lane & 3);
#pragma unroll
    for (int m = 0; m < 2; m++) {
        int ra = 32 * mw + 16 * m + (lane >> 2), rb = ra + 8;
        const float* ea = emb + (size_t)ten[ra] * kD + cb;
        const float* eb = emb + (size_t)ten[rb] * kD + cb;
        float* oa = out + ((size_t)b * 64 + ra) * kD + cb;
        float* ob = out + ((size_t)b * 64 + rb) * kD + cb;
#pragma unroll
        for (int nt = 0; nt < 4; nt++) {
            float2 ga = __ldg((const float2*)(ea + nt * 8));
            float2 gb = __ldg((const float2*)(eb + nt * 8));
            *(float2*)(oa + nt * 8) =
                make_float2(acc[m][nt][0] + ga.x, acc[m][nt][1] + ga.y);
            *(float2*)(ob + nt * 8) =
                make_float2(acc[m][nt][2] + gb.x, acc[m][nt][3] + gb.y);
        }
    }
}

// ---------------------------------------------------------------------------
extern "C" void kernel_launch(void* const* d_in, const int* in_sizes, int n_in,
                              void* d_out, int out_size) {
    (void)in_sizes; (void)n_in; (void)out_size;
    const int* ids_en = (const int*)d_in[0];
    const int* ids_fr = (const int*)d_in[1];
    const float* emb  = (const float*)d_in[2];
    const float* Wq   = (const float*)d_in[3];
    float* out        = (float*)d_out;

    proj_kernel<<<dim3(19, 16), 256>>>(emb, Wq);
    gram_kernel<<<dim3(10, 10), 256>>>();
    cudaFuncSetAttribute(sbuild_kernel, cudaFuncAttributeMaxDynamicSharedMemorySize,
                         SMEM_SB);
    sbuild_kernel<<<dim3(kB, 2), 256, SMEM_SB>>>(ids_fr);
    cudaFuncSetAttribute(main_kernel, cudaFuncAttributeMaxDynamicSharedMemorySize,
                         SMEM_MAIN);
    main_kernel<<<dim3(kB, 4), 256, SMEM_MAIN>>>(ids_en, ids_fr, emb, out);
}

// round 13
// speedup vs baseline: 1.5296x; 1.1300x over previous
#include <cuda_runtime.h>
#include <cuda_fp16.h>
#include <cstdint>

// ---------------------------------------------------------------------------
// out = emb[ids_en] + S @ V,  vocab collapse:
//   proj = emb @ Qdense [300,512] -> fp32 g_proj + fp16 g_pf16
//   G = proj projT -> packed fp16 {hi|lo} g_grams (stride 304, col 0 zeroed)
//   sbuild (per batch x 2 CTAs): gather 32 G rows coalesced, column-select ->
//     S hi/lo fp16 planes in global g_sp (L2-resident)
//   main (per batch x 4 column-CTAs, 3 CTAs/SM): enc = S @ V via fp16
//     2-PRODUCT mma: D = (S_hi + S_lo) * V_hi  (dropped S*V_lo ~ 2^-12,
//     random-sign accumulation -> rel_err ~1e-4 << 1e-3). No V_lo plane:
//     B ldsm halved, mma 96->64/warp, staging halved. out = enc + emb.
// (tcgen05 unavailable: harness builds through plain compute_103 PTX.)
// ---------------------------------------------------------------------------

namespace {
constexpr int kB = 1024;
constexpr int kV = 300;
constexpr int kVP = 304;      // g_grams row stride (words)
constexpr int kD = 512;
constexpr int kN = 128;       // cols per main CTA (batch split in 4)

// sbuild smem (32 G rows per CTA)
constexpr int GSTRB = 1216;                      // G row bytes (304 words)
constexpr int SB_TFR = 32 * GSTRB;               // 38,912
constexpr int SMEM_SB = SB_TFR + 256;            // 39,168 -> 5 CTAs/SM

// main smem
constexpr int PROW2 = 272;                       // P plane row stride (128 fp16 + 16B)
constexpr int SROWB = 144;                       // S plane row stride (64 fp16 + 16B)
constexpr int OFF_P   = 0;                       // single V_hi plane
constexpr int OFF_SHI = 64 * PROW2;              // 17,408
constexpr int OFF_SLO = OFF_SHI + 64 * SROWB;    // 26,624
constexpr int DSL     = OFF_SLO - OFF_SHI;
constexpr int OFF_TFR = OFF_SLO + 64 * SROWB;    // 35,840
constexpr int OFF_TEN = OFF_TFR + 256;
constexpr int SMEM_MAIN = OFF_TEN + 256;         // 36,352 -> 3 CTAs/SM (regs)
}

__device__ float    g_proj [kV * kD];        // fp32 proj (gram input)
__device__ __half   g_pf16 [kV * kD];        // fp16 proj (main B operand)
__device__ uint32_t g_grams[kV * kVP];       // packed {fp16 hi | fp16 lo}, col 0 = 0
__device__ uint32_t g_sp   [kB * 4096];      // per-batch S planes: [b][2][64][32]

// ---------------- helpers --------------------------------------------------
__device__ __forceinline__ uint32_t smem_u32(const void* p) {
    uint32_t a;
    asm("{ .reg .u64 t; cvta.to.shared.u64 t, %1; cvt.u32.u64 %0, t; }"
        : "=r"(a) : "l"(p));
    return a;
}
__device__ __forceinline__ uint32_t prmt(uint32_t a, uint32_t b, uint32_t sel) {
    uint32_t d;
    asm("prmt.b32 %0, %1, %2, %3;" : "=r"(d) : "r"(a), "r"(b), "r"(sel));
    return d;
}
__device__ __forceinline__ void ldsm4(uint32_t* r, uint32_t addr) {
    asm volatile("ldmatrix.sync.aligned.m8n8.x4.shared.b16 {%0,%1,%2,%3}, [%4];"
                 : "=r"(r[0]), "=r"(r[1]), "=r"(r[2]), "=r"(r[3]) : "r"(addr));
}
__device__ __forceinline__ void ldsm4t(uint32_t* r, uint32_t addr) {
    asm volatile("ldmatrix.sync.aligned.m8n8.x4.trans.shared.b16 {%0,%1,%2,%3}, [%4];"
                 : "=r"(r[0]), "=r"(r[1]), "=r"(r[2]), "=r"(r[3]) : "r"(addr));
}
__device__ __forceinline__ void mma_f16(float* c, const uint32_t* a,
                                        const uint32_t* b) {
    asm volatile(
        "mma.sync.aligned.m16n8k16.row.col.f32.f16.f16.f32 "
        "{%0,%1,%2,%3}, {%4,%5,%6,%7}, {%8,%9}, {%0,%1,%2,%3};"
        : "+f"(c[0]), "+f"(c[1]), "+f"(c[2]), "+f"(c[3])
        : "r"(a[0]), "r"(a[1]), "r"(a[2]), "r"(a[3]), "r"(b[0]), "r"(b[1]));
}
// fp32 -> packed {fp16 hi << 16 | fp16 residual lo}
__device__ __forceinline__ uint32_t pack_split16(float v) {
    __half h = __float2half_rn(v);
    float hf = __half2float(h);
    __half l = __float2half_rn(v - hf);
    return ((uint32_t)__half_as_ushort(h) << 16) | __half_as_ushort(l);
}

// ---------------------------------------------------------------------------
// Kernel 1: proj = emb @ Qdense -> g_proj fp32 + g_pf16. (tiling validated)
// ---------------------------------------------------------------------------
__global__ void __launch_bounds__(256) proj_kernel(const float* __restrict__ emb,
                                                   const float* __restrict__ Wq) {
    __shared__ float As[16 * 65];
    __shared__ float Bs[64 * 36];
    const int r0 = blockIdx.x * 16, c0 = blockIdx.y * 32;
    const int t = threadIdx.x;
    const int r = t & 15, cg = t >> 4;
    float2 acc = make_float2(0.f, 0.f);

    for (int kc = 0; kc < kD; kc += 64) {
        __syncthreads();
        {
            int ar = t >> 4, ak4 = t & 15;
            float4 v = make_float4(0.f, 0.f, 0.f, 0.f);
            if (r0 + ar < kV) v = *(const float4*)(emb + (r0 + ar) * kD + kc + ak4 * 4);
            float* d = As + ar * 65 + ak4 * 4;
            d[0] = v.x; d[1] = v.y; d[2] = v.z; d[3] = v.w;
        }
        {
            int c4 = t & 7;
#pragma unroll
            for (int j = 0; j < 2; j++) {
                int bk = (t >> 3) + 32 * j;
                float4 v = *(const float4*)(Wq + (kc + bk) * kD + c0 + c4 * 4);
                *(float4*)(Bs + bk * 36 + c4 * 4) = v;
            }
        }
        __syncthreads();
#pragma unroll 8
        for (int kk = 0; kk < 64; kk++) {
            float a = As[r * 65 + kk];
            float2 bv = *(const float2*)(Bs + kk * 36 + cg * 2);
            acc.x = fmaf(a, bv.x, acc.x);
            acc.y = fmaf(a, bv.y, acc.y);
        }
    }
    if (r0 + r < kV) {
        int idx = (r0 + r) * kD + c0 + cg * 2;
        *(float2*)(g_proj + idx) = acc;
        *(__half2*)(g_pf16 + idx) = __floats2half2_rn(acc.x, acc.y);
    }
}

// ---------------------------------------------------------------------------
// Kernel 2: G = proj projT -> packed fp16-split g_grams, col 0 zeroed.
// ---------------------------------------------------------------------------
__global__ void __launch_bounds__(256) gram_kernel() {
    __shared__ float As[32 * 130];
    __shared__ float Bs[32 * 130];
    const int i0 = blockIdx.x * 32, j0 = blockIdx.y * 32;
    const int t = threadIdx.x;
    const int tx = t & 15, ty = t >> 4;
    float a00 = 0.f, a01 = 0.f, a10 = 0.f, a11 = 0.f;

    for (int kc = 0; kc < kD; kc += 128) {
        __syncthreads();
        {
            int sr = t >> 3;
#pragma unroll
            for (int j = 0; j < 4; j++) {
                int c4 = (t & 7) + 8 * j;
                float4 va = make_float4(0.f, 0.f, 0.f, 0.f);
                float4 vb = make_float4(0.f, 0.f, 0.f, 0.f);
                if (i0 + sr < kV) va = *(const float4*)(g_proj + (i0 + sr) * kD + kc + c4 * 4);
                if (j0 + sr < kV) vb = *(const float4*)(g_proj + (j0 + sr) * kD + kc + c4 * 4);
                float2* da = (float2*)(As + sr * 130 + c4 * 4);
                float2* db = (float2*)(Bs + sr * 130 + c4 * 4);
                da[0] = make_float2(va.x, va.y); da[1] = make_float2(va.z, va.w);
                db[0] = make_float2(vb.x, vb.y); db[1] = make_float2(vb.z, vb.w);
            }
        }
        __syncthreads();
#pragma unroll 8
        for (int kk = 0; kk < 128; kk += 2) {
            float2 x0 = *(const float2*)(As + ty * 130 + kk);
            float2 x1 = *(const float2*)(As + (ty + 16) * 130 + kk);
            float2 y0 = *(const float2*)(Bs + tx * 130 + kk);
            float2 y1 = *(const float2*)(Bs + (tx + 16) * 130 + kk);
            a00 = fmaf(x0.x, y0.x, a00); a00 = fmaf(x0.y, y0.y, a00);
            a01 = fmaf(x0.x, y1.x, a01); a01 = fmaf(x0.y, y1.y, a01);
            a10 = fmaf(x1.x, y0.x, a10); a10 = fmaf(x1.y, y0.y, a10);
            a11 = fmaf(x1.x, y1.x, a11); a11 = fmaf(x1.y, y1.y, a11);
        }
    }
    int i = i0 + ty, j = j0 + tx;
    if (i < kV) {
        if (j < kV)      g_grams[i * kVP + j]      = j ? pack_split16(a00) : 0u;
        if (j + 16 < kV) g_grams[i * kVP + j + 16] = pack_split16(a01);
    }
    if (i + 16 < kV) {
        if (j < kV)      g_grams[(i + 16) * kVP + j]      = j ? pack_split16(a10) : 0u;
        if (j + 16 < kV) g_grams[(i + 16) * kVP + j + 16] = pack_split16(a11);
    }
}

// ---------------------------------------------------------------------------
// Kernel 3 (sbuild): grid (1024, 2); CTA = (batch, 32-q-row half).
// Stage 32 G rows coalesced (39 KB smem -> 5 CTAs/SM), column-select ->
// S hi/lo fp16 planes g_sp[b][2][64][32]. Mask pre-baked (G col 0 == 0).
// ---------------------------------------------------------------------------
__global__ void __launch_bounds__(256) sbuild_kernel(const int* __restrict__ ids_fr) {
    extern __shared__ char smem[];
    int* tfr = (int*)(smem + SB_TFR);
    const int b = blockIdx.x;
    const int h = blockIdx.y;
    const int tid = threadIdx.x;

    if (tid < 64) tfr[tid] = ids_fr[b * 64 + tid];
    __syncthreads();

    for (int idx = tid; idx < 32 * 76; idx += 256) {
        int r = idx / 76, c = idx - r * 76;
        ((uint4*)(smem + r * GSTRB))[c] =
            __ldg((const uint4*)(g_grams + (size_t)tfr[32 * h + r] * kVP) + c);
    }
    __syncthreads();

    uint32_t* sp = g_sp + ((size_t)b << 12);
    for (int t4 = tid; t4 < 1024; t4 += 256) {
        int i = t4 >> 5, kp = t4 & 31;
        int q = 32 * h + i;
        const uint32_t* grow = (const uint32_t*)(smem + i * GSTRB);
        uint32_t v0 = grow[tfr[2 * kp]];
        uint32_t v1 = grow[tfr[2 * kp + 1]];
        sp[(q << 5) + kp]        = prmt(v0, v1, 0x7632);   // hi plane
        sp[2048 + (q << 5) + kp] = prmt(v0, v1, 0x5410);   // lo plane
    }
}

// ---------------------------------------------------------------------------
// Kernel 4 (main): grid (1024, 4); CTA = (batch, 128-col quarter), 256 thr,
// 36.4 KB smem, ~76 regs -> 3 CTAs/SM. Warp tile 32q x 32n (warps 2m x 4n):
// per warp: 24 ldsm, 64 fp16 mma. D = (S_hi + S_lo) @ V_hi; out = D + emb.
// ---------------------------------------------------------------------------
__global__ void __launch_bounds__(256, 3) main_kernel(
    const int* __restrict__ ids_en, const int* __restrict__ ids_fr,
    const float* __restrict__ emb, float* __restrict__ out) {
    extern __shared__ char smem[];
    const uint32_t sb = smem_u32(smem);
    int* tfr = (int*)(smem + OFF_TFR);
    int* ten = (int*)(smem + OFF_TEN);

    const int b = blockIdx.x;
    const int coff = blockIdx.y * kN;
    const int tid = threadIdx.x;
    const int lane = tid & 31, w = tid >> 5;

    if (tid < 64)       tfr[tid]      = ids_fr[b * 64 + tid];
    else if (tid < 128) ten[tid - 64] = ids_en[b * 64 + (tid - 64)];
    __syncthreads();

    // ---- Load S planes (coalesced uint4): 1024 tasks, 4 per thread ----------
    {
        const uint4* sp = (const uint4*)(g_sp + ((size_t)b << 12));
#pragma unroll
        for (int i = 0; i < 4; i++) {
            int idx = tid + 256 * i;
            uint4 v = __ldg(sp + idx);
            int w4 = idx * 4;
            int p = w4 >> 11, rem = w4 & 2047;
            int q = rem >> 5, k0 = rem & 31;
            *(uint4*)(smem + (p ? OFF_SLO : OFF_SHI) + q * SROWB + k0 * 4) = v;
        }
    }
    // ---- Stage V_hi plane (64 x 128 fp16): straight copy, 1024 uint4 --------
#pragma unroll
    for (int i = 0; i < 4; i++) {
        int idx = tid + 256 * i;
        int r = idx >> 4, g = idx & 15;
        uint4 v = __ldg((const uint4*)(g_pf16 + (size_t)tfr[r] * kD + coff) + g);
        *(uint4*)(smem + OFF_P + r * PROW2 + g * 16) = v;
    }
    __syncthreads();

    // ---- MMA: warp tile 32q x 32n (warps: mw = w&1, nw = w>>1) -------------
    const int mw = w & 1, nw = w >> 1;
    const uint32_t aS = sb + OFF_SHI
        + (uint32_t)(32 * mw + (lane & 15)) * SROWB + ((lane >> 4) * 16);
    const uint32_t bT = sb + OFF_P + (uint32_t)(lane & 15) * PROW2
        + (uint32_t)(32 * nw + (lane >> 4) * 8) * 2;

    float acc[2][4][4];
#pragma unroll
    for (int m = 0; m < 2; m++)
#pragma unroll
        for (int nt = 0; nt < 4; nt++)
#pragma unroll
            for (int i = 0; i < 4; i++) acc[m][nt][i] = 0.f;

#pragma unroll
    for (int ks = 0; ks < 4; ks++) {
        uint32_t AH0[4], AH1[4], AL0[4], AL1[4];
        ldsm4(AH0, aS + ks * 32);
        ldsm4(AH1, aS + 16 * SROWB + ks * 32);
        ldsm4(AL0, aS + DSL + ks * 32);
        ldsm4(AL1, aS + DSL + 16 * SROWB + ks * 32);
        uint32_t adr = bT + (uint32_t)(ks * 16) * PROW2;
        uint32_t bH0[4], bH1[4];
        ldsm4t(bH0, adr);
        ldsm4t(bH1, adr + 32);

        mma_f16(acc[0][0], AH0, bH0);     mma_f16(acc[0][0], AL0, bH0);
        mma_f16(acc[0][1], AH0, bH0 + 2); mma_f16(acc[0][1], AL0, bH0 + 2);
        mma_f16(acc[0][2], AH0, bH1);     mma_f16(acc[0][2], AL0, bH1);
        mma_f16(acc[0][3], AH0, bH1 + 2); mma_f16(acc[0][3], AL0, bH1 + 2);

        mma_f16(acc[1][0], AH1, bH0);     mma_f16(acc[1][0], AL1, bH0);
        mma_f16(acc[1][1], AH1, bH0 + 2); mma_f16(acc[1][1], AL1, bH0 + 2);
        mma_f16(acc[1][2], AH1, bH1);     mma_f16(acc[1][2], AL1, bH1);
        mma_f16(acc[1][3], AH1, bH1 + 2); mma_f16(acc[1][3], AL1, bH1 + 2);
    }

    // ---- Epilogue: out = enc + emb[ids_en] ----------------------------------
    const int cb = coff + 32 * nw + 2 * (lane & 3);
#pragma unroll
    for (int m = 0; m < 2; m++) {
        int ra = 32 * mw + 16 * m + (lane >> 2), rb = ra + 8;
        const float* ea = emb + (size_t)ten[ra] * kD + cb;
        const float* eb = emb + (size_t)ten[rb] * kD + cb;
        float* oa = out + ((size_t)b * 64 + ra) * kD + cb;
        float* ob = out + ((size_t)b * 64 + rb) * kD + cb;
#pragma unroll
        for (int nt = 0; nt < 4; nt++) {
            float2 ga = __ldg((const float2*)(ea + nt * 8));
            float2 gb = __ldg((const float2*)(eb + nt * 8));
            *(float2*)(oa + nt * 8) =
                make_float2(acc[m][nt][0] + ga.x, acc[m][nt][1] + ga.y);
            *(float2*)(ob + nt * 8) =
                make_float2(acc[m][nt][2] + gb.x, acc[m][nt][3] + gb.y);
        }
    }
}

// ---------------------------------------------------------------------------
extern "C" void kernel_launch(void* const* d_in, const int* in_sizes, int n_in,
                              void* d_out, int out_size) {
    (void)in_sizes; (void)n_in; (void)out_size;
    const int* ids_en = (const int*)d_in[0];
    const int* ids_fr = (const int*)d_in[1];
    const float* emb  = (const float*)d_in[2];
    const float* Wq   = (const float*)d_in[3];
    float* out        = (float*)d_out;

    proj_kernel<<<dim3(19, 16), 256>>>(emb, Wq);
    gram_kernel<<<dim3(10, 10), 256>>>();
    cudaFuncSetAttribute(sbuild_kernel, cudaFuncAttributeMaxDynamicSharedMemorySize,
                         SMEM_SB);
    sbuild_kernel<<<dim3(kB, 2), 256, SMEM_SB>>>(ids_fr);
    cudaFuncSetAttribute(main_kernel, cudaFuncAttributeMaxDynamicSharedMemorySize,
                         SMEM_MAIN);
    main_kernel<<<dim3(kB, 4), 256, SMEM_MAIN>>>(ids_en, ids_fr, emb, out);
}

// round 14
// speedup vs baseline: 1.5301x; 1.0003x over previous
#include <cuda_runtime.h>
#include <cuda_fp16.h>
#include <cstdint>

// ---------------------------------------------------------------------------
// out = emb[ids_en] + S @ V,  vocab collapse:
//   proj = emb @ Qdense [300,512] -> fp32 g_proj + fp16 g_pf16
//   G = proj projT -> packed fp16 {hi|lo} g_grams (stride 304, col 0 zeroed)
//   sbuild (per batch x 2 CTAs): gather 32 G rows coalesced, column-select ->
//     S hi/lo fp16 planes in global g_sp (L2-resident)
//   main (per batch x 4 column-CTAs, 128 thr, 4 CTAs/SM): enc = S @ V via
//     fp16 2-product mma  D = (S_hi + S_lo) * V_hi  with 32q x 64n warp
//     tiles (ldsm:mma = 32:128 per warp, 33% fewer ldsm than 32x32).
//     out = enc + emb[ids_en].
// (tcgen05 unavailable: harness builds through plain compute_103 PTX.)
// ---------------------------------------------------------------------------

namespace {
constexpr int kB = 1024;
constexpr int kV = 300;
constexpr int kVP = 304;      // g_grams row stride (words)
constexpr int kD = 512;
constexpr int kN = 128;       // cols per main CTA (batch split in 4)

// sbuild smem (32 G rows per CTA)
constexpr int GSTRB = 1216;                      // G row bytes (304 words)
constexpr int SB_TFR = 32 * GSTRB;               // 38,912
constexpr int SMEM_SB = SB_TFR + 256;            // 39,168 -> 5 CTAs/SM

// main smem
constexpr int PROW2 = 272;                       // P plane row stride (128 fp16 + 16B)
constexpr int SROWB = 144;                       // S plane row stride (64 fp16 + 16B)
constexpr int OFF_P   = 0;                       // single V_hi plane
constexpr int OFF_SHI = 64 * PROW2;              // 17,408
constexpr int OFF_SLO = OFF_SHI + 64 * SROWB;    // 26,624
constexpr int DSL     = OFF_SLO - OFF_SHI;
constexpr int OFF_TFR = OFF_SLO + 64 * SROWB;    // 35,840
constexpr int OFF_TEN = OFF_TFR + 256;
constexpr int SMEM_MAIN = OFF_TEN + 256;         // 36,352 -> 4 CTAs/SM
}

__device__ float    g_proj [kV * kD];        // fp32 proj (gram input)
__device__ __half   g_pf16 [kV * kD];        // fp16 proj (main B operand)
__device__ uint32_t g_grams[kV * kVP];       // packed {fp16 hi | fp16 lo}, col 0 = 0
__device__ uint32_t g_sp   [kB * 4096];      // per-batch S planes: [b][2][64][32]

// ---------------- helpers --------------------------------------------------
__device__ __forceinline__ uint32_t smem_u32(const void* p) {
    uint32_t a;
    asm("{ .reg .u64 t; cvta.to.shared.u64 t, %1; cvt.u32.u64 %0, t; }"
        : "=r"(a) : "l"(p));
    return a;
}
__device__ __forceinline__ uint32_t prmt(uint32_t a, uint32_t b, uint32_t sel) {
    uint32_t d;
    asm("prmt.b32 %0, %1, %2, %3;" : "=r"(d) : "r"(a), "r"(b), "r"(sel));
    return d;
}
__device__ __forceinline__ void ldsm4(uint32_t* r, uint32_t addr) {
    asm volatile("ldmatrix.sync.aligned.m8n8.x4.shared.b16 {%0,%1,%2,%3}, [%4];"
                 : "=r"(r[0]), "=r"(r[1]), "=r"(r[2]), "=r"(r[3]) : "r"(addr));
}
__device__ __forceinline__ void ldsm4t(uint32_t* r, uint32_t addr) {
    asm volatile("ldmatrix.sync.aligned.m8n8.x4.trans.shared.b16 {%0,%1,%2,%3}, [%4];"
                 : "=r"(r[0]), "=r"(r[1]), "=r"(r[2]), "=r"(r[3]) : "r"(addr));
}
__device__ __forceinline__ void mma_f16(float* c, const uint32_t* a,
                                        const uint32_t* b) {
    asm volatile(
        "mma.sync.aligned.m16n8k16.row.col.f32.f16.f16.f32 "
        "{%0,%1,%2,%3}, {%4,%5,%6,%7}, {%8,%9}, {%0,%1,%2,%3};"
        : "+f"(c[0]), "+f"(c[1]), "+f"(c[2]), "+f"(c[3])
        : "r"(a[0]), "r"(a[1]), "r"(a[2]), "r"(a[3]), "r"(b[0]), "r"(b[1]));
}
// fp32 -> packed {fp16 hi << 16 | fp16 residual lo}
__device__ __forceinline__ uint32_t pack_split16(float v) {
    __half h = __float2half_rn(v);
    float hf = __half2float(h);
    __half l = __float2half_rn(v - hf);
    return ((uint32_t)__half_as_ushort(h) << 16) | __half_as_ushort(l);
}

// ---------------------------------------------------------------------------
// Kernel 1: proj = emb @ Qdense -> g_proj fp32 + g_pf16. (validated)
// ---------------------------------------------------------------------------
__global__ void __launch_bounds__(256) proj_kernel(const float* __restrict__ emb,
                                                   const float* __restrict__ Wq) {
    __shared__ float As[16 * 65];
    __shared__ float Bs[64 * 36];
    const int r0 = blockIdx.x * 16, c0 = blockIdx.y * 32;
    const int t = threadIdx.x;
    const int r = t & 15, cg = t >> 4;
    float2 acc = make_float2(0.f, 0.f);

    for (int kc = 0; kc < kD; kc += 64) {
        __syncthreads();
        {
            int ar = t >> 4, ak4 = t & 15;
            float4 v = make_float4(0.f, 0.f, 0.f, 0.f);
            if (r0 + ar < kV) v = *(const float4*)(emb + (r0 + ar) * kD + kc + ak4 * 4);
            float* d = As + ar * 65 + ak4 * 4;
            d[0] = v.x; d[1] = v.y; d[2] = v.z; d[3] = v.w;
        }
        {
            int c4 = t & 7;
#pragma unroll
            for (int j = 0; j < 2; j++) {
                int bk = (t >> 3) + 32 * j;
                float4 v = *(const float4*)(Wq + (kc + bk) * kD + c0 + c4 * 4);
                *(float4*)(Bs + bk * 36 + c4 * 4) = v;
            }
        }
        __syncthreads();
#pragma unroll 8
        for (int kk = 0; kk < 64; kk++) {
            float a = As[r * 65 + kk];
            float2 bv = *(const float2*)(Bs + kk * 36 + cg * 2);
            acc.x = fmaf(a, bv.x, acc.x);
            acc.y = fmaf(a, bv.y, acc.y);
        }
    }
    if (r0 + r < kV) {
        int idx = (r0 + r) * kD + c0 + cg * 2;
        *(float2*)(g_proj + idx) = acc;
        *(__half2*)(g_pf16 + idx) = __floats2half2_rn(acc.x, acc.y);
    }
}

// ---------------------------------------------------------------------------
// Kernel 2: G = proj projT -> packed fp16-split g_grams, col 0 zeroed.
// ---------------------------------------------------------------------------
__global__ void __launch_bounds__(256) gram_kernel() {
    __shared__ float As[32 * 130];
    __shared__ float Bs[32 * 130];
    const int i0 = blockIdx.x * 32, j0 = blockIdx.y * 32;
    const int t = threadIdx.x;
    const int tx = t & 15, ty = t >> 4;
    float a00 = 0.f, a01 = 0.f, a10 = 0.f, a11 = 0.f;

    for (int kc = 0; kc < kD; kc += 128) {
        __syncthreads();
        {
            int sr = t >> 3;
#pragma unroll
            for (int j = 0; j < 4; j++) {
                int c4 = (t & 7) + 8 * j;
                float4 va = make_float4(0.f, 0.f, 0.f, 0.f);
                float4 vb = make_float4(0.f, 0.f, 0.f, 0.f);
                if (i0 + sr < kV) va = *(const float4*)(g_proj + (i0 + sr) * kD + kc + c4 * 4);
                if (j0 + sr < kV) vb = *(const float4*)(g_proj + (j0 + sr) * kD + kc + c4 * 4);
                float2* da = (float2*)(As + sr * 130 + c4 * 4);
                float2* db = (float2*)(Bs + sr * 130 + c4 * 4);
                da[0] = make_float2(va.x, va.y); da[1] = make_float2(va.z, va.w);
                db[0] = make_float2(vb.x, vb.y); db[1] = make_float2(vb.z, vb.w);
            }
        }
        __syncthreads();
#pragma unroll 8
        for (int kk = 0; kk < 128; kk += 2) {
            float2 x0 = *(const float2*)(As + ty * 130 + kk);
            float2 x1 = *(const float2*)(As + (ty + 16) * 130 + kk);
            float2 y0 = *(const float2*)(Bs + tx * 130 + kk);
            float2 y1 = *(const float2*)(Bs + (tx + 16) * 130 + kk);
            a00 = fmaf(x0.x, y0.x, a00); a00 = fmaf(x0.y, y0.y, a00);
            a01 = fmaf(x0.x, y1.x, a01); a01 = fmaf(x0.y, y1.y, a01);
            a10 = fmaf(x1.x, y0.x, a10); a10 = fmaf(x1.y, y0.y, a10);
            a11 = fmaf(x1.x, y1.x, a11); a11 = fmaf(x1.y, y1.y, a11);
        }
    }
    int i = i0 + ty, j = j0 + tx;
    if (i < kV) {
        if (j < kV)      g_grams[i * kVP + j]      = j ? pack_split16(a00) : 0u;
        if (j + 16 < kV) g_grams[i * kVP + j + 16] = pack_split16(a01);
    }
    if (i + 16 < kV) {
        if (j < kV)      g_grams[(i + 16) * kVP + j]      = j ? pack_split16(a10) : 0u;
        if (j + 16 < kV) g_grams[(i + 16) * kVP + j + 16] = pack_split16(a11);
    }
}

// ---------------------------------------------------------------------------
// Kernel 3 (sbuild): grid (1024, 2); CTA = (batch, 32-q-row half).
// Stage 32 G rows coalesced (39 KB smem -> 5 CTAs/SM), column-select ->
// S hi/lo fp16 planes g_sp[b][2][64][32]. Mask pre-baked (G col 0 == 0).
// ---------------------------------------------------------------------------
__global__ void __launch_bounds__(256) sbuild_kernel(const int* __restrict__ ids_fr) {
    extern __shared__ char smem[];
    int* tfr = (int*)(smem + SB_TFR);
    const int b = blockIdx.x;
    const int h = blockIdx.y;
    const int tid = threadIdx.x;

    if (tid < 64) tfr[tid] = ids_fr[b * 64 + tid];
    __syncthreads();

    for (int idx = tid; idx < 32 * 76; idx += 256) {
        int r = idx / 76, c = idx - r * 76;
        ((uint4*)(smem + r * GSTRB))[c] =
            __ldg((const uint4*)(g_grams + (size_t)tfr[32 * h + r] * kVP) + c);
    }
    __syncthreads();

    uint32_t* sp = g_sp + ((size_t)b << 12);
    for (int t4 = tid; t4 < 1024; t4 += 256) {
        int i = t4 >> 5, kp = t4 & 31;
        int q = 32 * h + i;
        const uint32_t* grow = (const uint32_t*)(smem + i * GSTRB);
        uint32_t v0 = grow[tfr[2 * kp]];
        uint32_t v1 = grow[tfr[2 * kp + 1]];
        sp[(q << 5) + kp]        = prmt(v0, v1, 0x7632);   // hi plane
        sp[2048 + (q << 5) + kp] = prmt(v0, v1, 0x5410);   // lo plane
    }
}

// ---------------------------------------------------------------------------
// Kernel 4 (main): grid (1024, 4); CTA = (batch, 128-col quarter), 128 thr,
// 36.4 KB smem, reg-cap 128 -> 4 CTAs/SM (16 warps/SM). Warp tile 32q x 64n
// (warps 2m x 2n): per warp 32 ldsm / 128 fp16 mma. out = enc + emb.
// ---------------------------------------------------------------------------
__global__ void __launch_bounds__(128, 4) main_kernel(
    const int* __restrict__ ids_en, const int* __restrict__ ids_fr,
    const float* __restrict__ emb, float* __restrict__ out) {
    extern __shared__ char smem[];
    const uint32_t sb = smem_u32(smem);
    int* tfr = (int*)(smem + OFF_TFR);
    int* ten = (int*)(smem + OFF_TEN);

    const int b = blockIdx.x;
    const int coff = blockIdx.y * kN;
    const int tid = threadIdx.x;
    const int lane = tid & 31, w = tid >> 5;

    if (tid < 64) {
        tfr[tid] = ids_fr[b * 64 + tid];
        ten[tid] = ids_en[b * 64 + tid];
    }
    __syncthreads();

    // ---- Load S planes (coalesced uint4): 1024 tasks, 8 per thread ----------
    {
        const uint4* sp = (const uint4*)(g_sp + ((size_t)b << 12));
#pragma unroll
        for (int i = 0; i < 8; i++) {
            int idx = tid + 128 * i;
            uint4 v = __ldg(sp + idx);
            int w4 = idx * 4;
            int p = w4 >> 11, rem = w4 & 2047;
            int q = rem >> 5, k0 = rem & 31;
            *(uint4*)(smem + (p ? OFF_SLO : OFF_SHI) + q * SROWB + k0 * 4) = v;
        }
    }
    // ---- Stage V_hi plane (64 x 128 fp16): straight copy, 1024 uint4 --------
#pragma unroll
    for (int i = 0; i < 8; i++) {
        int idx = tid + 128 * i;
        int r = idx >> 4, g = idx & 15;
        uint4 v = __ldg((const uint4*)(g_pf16 + (size_t)tfr[r] * kD + coff) + g);
        *(uint4*)(smem + OFF_P + r * PROW2 + g * 16) = v;
    }
    __syncthreads();

    // ---- MMA: warp tile 32q x 64n (warps: mw = w&1, nw = w>>1) -------------
    const int mw = w & 1, nw = w >> 1;
    const uint32_t aS = sb + OFF_SHI
        + (uint32_t)(32 * mw + (lane & 15)) * SROWB + ((lane >> 4) * 16);
    const uint32_t bT = sb + OFF_P + (uint32_t)(lane & 15) * PROW2
        + (uint32_t)(64 * nw + (lane >> 4) * 8) * 2;

    float acc[2][8][4];
#pragma unroll
    for (int m = 0; m < 2; m++)
#pragma unroll
        for (int nt = 0; nt < 8; nt++)
#pragma unroll
            for (int i = 0; i < 4; i++) acc[m][nt][i] = 0.f;

#pragma unroll
    for (int ks = 0; ks < 4; ks++) {
        uint32_t AH0[4], AH1[4], AL0[4], AL1[4];
        ldsm4(AH0, aS + ks * 32);
        ldsm4(AH1, aS + 16 * SROWB + ks * 32);
        ldsm4(AL0, aS + DSL + ks * 32);
        ldsm4(AL1, aS + DSL + 16 * SROWB + ks * 32);
        uint32_t adr = bT + (uint32_t)(ks * 16) * PROW2;
#pragma unroll
        for (int j = 0; j < 2; j++) {          // two 32-col halves of the 64n tile
            uint32_t bH0[4], bH1[4];
            ldsm4t(bH0, adr + j * 64);
            ldsm4t(bH1, adr + j * 64 + 32);
            float* a0 = acc[0][4 * j];
            float* a1 = acc[1][4 * j];
            mma_f16(a0,      AH0, bH0);     mma_f16(a0,      AL0, bH0);
            mma_f16(a0 + 4,  AH0, bH0 + 2); mma_f16(a0 + 4,  AL0, bH0 + 2);
            mma_f16(a0 + 8,  AH0, bH1);     mma_f16(a0 + 8,  AL0, bH1);
            mma_f16(a0 + 12, AH0, bH1 + 2); mma_f16(a0 + 12, AL0, bH1 + 2);
            mma_f16(a1,      AH1, bH0);     mma_f16(a1,      AL1, bH0);
            mma_f16(a1 + 4,  AH1, bH0 + 2); mma_f16(a1 + 4,  AL1, bH0 + 2);
            mma_f16(a1 + 8,  AH1, bH1);     mma_f16(a1 + 8,  AL1, bH1);
            mma_f16(a1 + 12, AH1, bH1 + 2); mma_f16(a1 + 12, AL1, bH1 + 2);
        }
    }

    // ---- Epilogue: out = enc + emb[ids_en] ----------------------------------
    const int cb = coff + 64 * nw + 2 * (lane & 3);
#pragma unroll
    for (int m = 0; m < 2; m++) {
        int ra = 32 * mw + 16 * m + (lane >> 2), rb = ra + 8;
        const float* ea = emb + (size_t)ten[ra] * kD + cb;
        const float* eb = emb + (size_t)ten[rb] * kD + cb;
        float* oa = out + ((size_t)b * 64 + ra) * kD + cb;
        float* ob = out + ((size_t)b * 64 + rb) * kD + cb;
#pragma unroll
        for (int nt = 0; nt < 8; nt++) {
            float2 ga = __ldg((const float2*)(ea + nt * 8));
            float2 gb = __ldg((const float2*)(eb + nt * 8));
            *(float2*)(oa + nt * 8) =
                make_float2(acc[m][nt][0] + ga.x, acc[m][nt][1] + ga.y);
            *(float2*)(ob + nt * 8) =
                make_float2(acc[m][nt][2] + gb.x, acc[m][nt][3] + gb.y);
        }
    }
}

// ---------------------------------------------------------------------------
extern "C" void kernel_launch(void* const* d_in, const int* in_sizes, int n_in,
                              void* d_out, int out_size) {
    (void)in_sizes; (void)n_in; (void)out_size;
    const int* ids_en = (const int*)d_in[0];
    const int* ids_fr = (const int*)d_in[1];
    const float* emb  = (const float*)d_in[2];
    const float* Wq   = (const float*)d_in[3];
    float* out        = (float*)d_out;

    proj_kernel<<<dim3(19, 16), 256>>>(emb, Wq);
    gram_kernel<<<dim3(10, 10), 256>>>();
    cudaFuncSetAttribute(sbuild_kernel, cudaFuncAttributeMaxDynamicSharedMemorySize,
                         SMEM_SB);
    sbuild_kernel<<<dim3(kB, 2), 256, SMEM_SB>>>(ids_fr);
    cudaFuncSetAttribute(main_kernel, cudaFuncAttributeMaxDynamicSharedMemorySize,
                         SMEM_MAIN);
    main_kernel<<<dim3(kB, 4), 128, SMEM_MAIN>>>(ids_en, ids_fr, emb, out);
}